// round 13
// baseline (speedup 1.0000x reference)
#include <cuda_runtime.h>
#include <cuda_fp16.h>
#include <cstdint>
#include <cstddef>

// ---------------------------------------------------------------------------
// Transformer forward, R13: R12 + fused attention (scores+softmax+ctx in one
// kernel; P round-trips through L2 within the block).
// ---------------------------------------------------------------------------

#define BB   2
#define SS   512
#define DD   1024
#define HH   16
#define DKK  64
#define DFFF 4096
#define LL   4
#define MROWS (BB*SS)          // 1024
#define EPSF 1e-5f
#define INV_SCALE 0.125f       // 1/sqrt(DK)

static const size_t MEG = 1u << 20;
__device__ __align__(16) float g_scratch[89u * (1u << 20)];   // 356 MB

// ---------------------------------------------------------------------------
// helpers
// ---------------------------------------------------------------------------
__device__ __forceinline__ uint32_t pk(float lo, float hi) {
    __half2 h = __floats2half2_rn(lo, hi);
    return *(uint32_t*)&h;
}
__device__ __forceinline__ uint2 pk4(float4 v) {
    return make_uint2(pk(v.x, v.y), pk(v.z, v.w));
}
__device__ __forceinline__ uint4 permT(uint2 e, uint2 o) {
    uint4 r;
    r.x = __byte_perm(e.x, o.x, 0x5410);
    r.y = __byte_perm(e.x, o.x, 0x7632);
    r.z = __byte_perm(e.y, o.y, 0x5410);
    r.w = __byte_perm(e.y, o.y, 0x7632);
    return r;
}
__device__ __forceinline__ void mma16(float* c, const uint32_t* a, const uint32_t* b) {
    asm volatile(
        "mma.sync.aligned.m16n8k16.row.col.f32.f16.f16.f32 "
        "{%0,%1,%2,%3}, {%4,%5,%6,%7}, {%8,%9}, {%0,%1,%2,%3};\n"
        : "+f"(c[0]), "+f"(c[1]), "+f"(c[2]), "+f"(c[3])
        : "r"(a[0]), "r"(a[1]), "r"(a[2]), "r"(a[3]), "r"(b[0]), "r"(b[1]));
}
__device__ __forceinline__ uint32_t smaddr(const void* p) {
    return (uint32_t)__cvta_generic_to_shared(p);
}
__device__ __forceinline__ void cpa16(uint32_t dsm, const void* gsrc) {
    asm volatile("cp.async.cg.shared.global [%0], [%1], 16;" :: "r"(dsm), "l"(gsrc));
}
#define CP_COMMIT() asm volatile("cp.async.commit_group;")
#define CP_WAIT2()  asm volatile("cp.async.wait_group 2;")

// ---------------------------------------------------------------------------
// Prepass: fp32 -> fp16 convert
// ---------------------------------------------------------------------------
__global__ __launch_bounds__(256)
void cvt16(const float* __restrict__ x, __half* __restrict__ y, int n)
{
    const int i = (blockIdx.x * 256 + threadIdx.x) * 4;
    if (i < n) {
        float4 v = *(const float4*)&x[i];
        *(uint2*)&y[i] = pk4(v);
    }
}

// Batched transpose+convert W[K,N] fp32 -> Wt[N,K] fp16.
__global__ __launch_bounds__(256)
void tcvt(const float* __restrict__ src, __half* __restrict__ dst, int K, int N)
{
    const size_t zoff = (size_t)blockIdx.z * K * N;
    src += zoff; dst += zoff;
    __shared__ float tile[32][33];
    const int t = threadIdx.x;
    const int tx = (t & 7) * 4, ty = t >> 3;
    const int x0 = blockIdx.x * 32, y0 = blockIdx.y * 32;

    float4 v = *(const float4*)&src[(size_t)(y0 + ty) * N + x0 + tx];
    tile[ty][tx] = v.x; tile[ty][tx + 1] = v.y;
    tile[ty][tx + 2] = v.z; tile[ty][tx + 3] = v.w;
    __syncthreads();

    const float a = tile[tx][ty], b = tile[tx + 1][ty];
    const float c = tile[tx + 2][ty], d = tile[tx + 3][ty];
    *(uint2*)&dst[(size_t)(x0 + ty) * K + y0 + tx] = make_uint2(pk(a, b), pk(c, d));
}

// ---------------------------------------------------------------------------
// Wide GEMM: fp16 A[M][K] @ fp16 Wt[N][K] -> fp16 C (+fp32 bias, opt ReLU).
// 64x128 tile, 256 thr, cp.async 4-stage. Dyn smem 61440 B.
// ---------------------------------------------------------------------------
__global__ __launch_bounds__(256, 2)
void gemm_wide_h(const __half* __restrict__ A, const __half* __restrict__ Wt,
                 const float* __restrict__ bias, __half* __restrict__ C,
                 int K, int nb, int relu,
                 long long wstride, long long bstride, long long cstride)
{
    constexpr int ASTR = 20, BSTR = 20;
    constexpr int ASZ = 64 * ASTR, BSZ = 128 * BSTR, STG = ASZ + BSZ;
    extern __shared__ uint32_t smg[];

    const int t = threadIdx.x, lane = t & 31, w = t >> 5;
    const int g = lane >> 2, cc = lane & 3;
    const int wm = w >> 2, wn = w & 3;
    const int row0 = blockIdx.y * 64;
    const int colg = blockIdx.x * 128;
    const int blk  = colg / nb;
    const int col0 = colg - blk * nb;
    const __half* Wp = Wt + (size_t)blk * (size_t)wstride;
    const float* bp = bias + (size_t)blk * (size_t)bstride;
    __half* Cp = C + (size_t)blk * (size_t)cstride;

    const uint32_t sb = smaddr(smg);
    const int arow = t >> 2, ach = t & 3;

    auto issue = [&](int it) {
        const int k0 = it << 5;
        const uint32_t base = sb + (uint32_t)((it & 3) * STG) * 4u;
        cpa16(base + (uint32_t)(arow * ASTR + ach * 4) * 4u,
              A + (size_t)(row0 + arow) * K + k0 + ach * 8);
#pragma unroll
        for (int i = 0; i < 2; i++) {
            const int idx = t + i * 256;
            const int br = idx >> 2, bch = idx & 3;
            cpa16(base + (uint32_t)(ASZ + br * BSTR + bch * 4) * 4u,
                  Wp + (size_t)(col0 + br) * K + k0 + bch * 8);
        }
    };

    float acc[2][4][4] = {};
    const int NK = K >> 5;
    issue(0); CP_COMMIT();
    issue(1); CP_COMMIT();
    issue(2); CP_COMMIT();

    for (int it = 0; it < NK; it++) {
        CP_WAIT2();
        __syncthreads();
        if (it + 3 < NK) issue(it + 3);
        CP_COMMIT();

        const uint32_t* as_ = smg + (it & 3) * STG;
        const uint32_t* bs_ = smg + (it & 3) * STG + ASZ;
        uint32_t af[2][4], bf[4][2];
#pragma unroll
        for (int ksi = 0; ksi < 2; ksi++) {
            const int kp = ksi * 8 + cc;
#pragma unroll
            for (int mi = 0; mi < 2; mi++) {
                const int mb = wm * 32 + mi * 16;
                af[mi][0] = as_[(mb + g) * ASTR + kp];
                af[mi][1] = as_[(mb + g + 8) * ASTR + kp];
                af[mi][2] = as_[(mb + g) * ASTR + kp + 4];
                af[mi][3] = as_[(mb + g + 8) * ASTR + kp + 4];
            }
#pragma unroll
            for (int nj = 0; nj < 4; nj++) {
                const int nrow = wn * 32 + nj * 8 + g;
                bf[nj][0] = bs_[nrow * BSTR + kp];
                bf[nj][1] = bs_[nrow * BSTR + kp + 4];
            }
#pragma unroll
            for (int mi = 0; mi < 2; mi++)
#pragma unroll
                for (int nj = 0; nj < 4; nj++)
                    mma16(acc[mi][nj], af[mi], bf[nj]);
        }
    }

#pragma unroll
    for (int mi = 0; mi < 2; mi++) {
        const int r0 = row0 + wm * 32 + mi * 16 + g;
#pragma unroll
        for (int nj = 0; nj < 4; nj++) {
            const int c = col0 + wn * 32 + nj * 8 + 2 * cc;
            const float b0v = bp[c], b1v = bp[c + 1];
            float v0 = acc[mi][nj][0] + b0v, v1 = acc[mi][nj][1] + b1v;
            float v2 = acc[mi][nj][2] + b0v, v3 = acc[mi][nj][3] + b1v;
            if (relu) {
                v0 = fmaxf(v0, 0.f); v1 = fmaxf(v1, 0.f);
                v2 = fmaxf(v2, 0.f); v3 = fmaxf(v3, 0.f);
            }
            *(uint32_t*)&Cp[(size_t)r0 * nb + c]       = pk(v0, v1);
            *(uint32_t*)&Cp[(size_t)(r0 + 8) * nb + c] = pk(v2, v3);
        }
    }
}

// ---------------------------------------------------------------------------
// 128-thread 64x64 cp.async core (fp16 A, fp16 Wt rows).
// ---------------------------------------------------------------------------
#define GEMMH64_CORE(AP, WP, LDA, LDW, NKV)                                     \
    constexpr int ASTR = 20, BSTR = 20;                                         \
    constexpr int ASZ = 64 * ASTR, BSZ = 64 * BSTR, STG = ASZ + BSZ;            \
    __shared__ uint32_t smg[4 * STG];                                           \
    const int t = threadIdx.x, lane = t & 31, w = t >> 5;                       \
    const int g = lane >> 2, cc = lane & 3;                                     \
    const int wm = w >> 1, wn = w & 1;                                          \
    const int row0 = blockIdx.y * 64;                                           \
    const int col0 = blockIdx.x * 64;                                           \
    const uint32_t sb = smaddr(smg);                                            \
    auto issue = [&](int it) {                                                  \
        const int k0 = it << 5;                                                 \
        const uint32_t base = sb + (uint32_t)((it & 3) * STG) * 4u;             \
        _Pragma("unroll")                                                       \
        for (int i = 0; i < 2; i++) {                                           \
            const int idx = t + i * 128;                                        \
            const int r = idx >> 2, ch = idx & 3;                               \
            cpa16(base + (uint32_t)(r * ASTR + ch * 4) * 4u,                    \
                  AP + (size_t)(row0 + r) * LDA + k0 + ch * 8);                 \
            cpa16(base + (uint32_t)(ASZ + r * BSTR + ch * 4) * 4u,              \
                  WP + (size_t)(col0 + r) * LDW + k0 + ch * 8);                 \
        }                                                                       \
    };                                                                          \
    float acc[2][4][4] = {};                                                    \
    const int NK = (NKV);                                                       \
    issue(0); CP_COMMIT();                                                      \
    issue(1); CP_COMMIT();                                                      \
    issue(2); CP_COMMIT();                                                      \
    for (int it = 0; it < NK; it++) {                                           \
        CP_WAIT2();                                                             \
        __syncthreads();                                                        \
        if (it + 3 < NK) issue(it + 3);                                         \
        CP_COMMIT();                                                            \
        const uint32_t* as_ = smg + (it & 3) * STG;                             \
        const uint32_t* bs_ = smg + (it & 3) * STG + ASZ;                       \
        uint32_t af[2][4], bf[4][2];                                            \
        _Pragma("unroll")                                                       \
        for (int ksi = 0; ksi < 2; ksi++) {                                     \
            const int kp = ksi * 8 + cc;                                        \
            _Pragma("unroll")                                                   \
            for (int mi = 0; mi < 2; mi++) {                                    \
                const int mb = wm * 32 + mi * 16;                               \
                af[mi][0] = as_[(mb + g) * ASTR + kp];                          \
                af[mi][1] = as_[(mb + g + 8) * ASTR + kp];                      \
                af[mi][2] = as_[(mb + g) * ASTR + kp + 4];                      \
                af[mi][3] = as_[(mb + g + 8) * ASTR + kp + 4];                  \
            }                                                                   \
            _Pragma("unroll")                                                   \
            for (int nj = 0; nj < 4; nj++) {                                    \
                const int nrow = wn * 32 + nj * 8 + g;                          \
                bf[nj][0] = bs_[nrow * BSTR + kp];                              \
                bf[nj][1] = bs_[nrow * BSTR + kp + 4];                          \
            }                                                                   \
            _Pragma("unroll")                                                   \
            for (int mi = 0; mi < 2; mi++)                                      \
                _Pragma("unroll")                                               \
                for (int nj = 0; nj < 4; nj++)                                  \
                    mma16(acc[mi][nj], af[mi], bf[nj]);                         \
        }                                                                       \
    }

// cross-Q: fp16 A @ Wt + bias -> fp16 C.
__global__ __launch_bounds__(128, 4)
void gemm_h64(const __half* __restrict__ A, const __half* __restrict__ Wt,
              const float* __restrict__ bias, __half* __restrict__ C)
{
    GEMMH64_CORE(A, Wt, 1024, 1024, 32)
#pragma unroll
    for (int mi = 0; mi < 2; mi++) {
        const int r0 = row0 + wm * 32 + mi * 16 + g;
#pragma unroll
        for (int nj = 0; nj < 4; nj++) {
            const int c = col0 + wn * 32 + nj * 8 + 2 * cc;
            const float b0v = bias[c], b1v = bias[c + 1];
            *(uint32_t*)&C[(size_t)r0 * 1024 + c] =
                pk(acc[mi][nj][0] + b0v, acc[mi][nj][1] + b1v);
            *(uint32_t*)&C[(size_t)(r0 + 8) * 1024 + c] =
                pk(acc[mi][nj][2] + b0v, acc[mi][nj][3] + b1v);
        }
    }
}

// Split-K: parts[z] = A[:, zKc:(z+1)Kc] @ Wt-cols-slice. Grid (16,16,nsplit).
__global__ __launch_bounds__(128, 4)
void gemm_sk_h(const __half* __restrict__ A, const __half* __restrict__ Wt,
               float* __restrict__ parts, int lda, int ldw, int Kc)
{
    const int z = blockIdx.z;
    const __half* Az = A + (size_t)z * Kc;
    const __half* Wz = Wt + (size_t)z * Kc;
    float* Cp = parts + (size_t)z * MEG;
    GEMMH64_CORE(Az, Wz, lda, ldw, (Kc >> 5))
#pragma unroll
    for (int mi = 0; mi < 2; mi++) {
        const int r0 = row0 + wm * 32 + mi * 16 + g;
#pragma unroll
        for (int nj = 0; nj < 4; nj++) {
            const int c = col0 + wn * 32 + nj * 8 + 2 * cc;
            *(float2*)&Cp[(size_t)r0 * 1024 + c] =
                make_float2(acc[mi][nj][0], acc[mi][nj][1]);
            *(float2*)&Cp[(size_t)(r0 + 8) * 1024 + c] =
                make_float2(acc[mi][nj][2], acc[mi][nj][3]);
        }
    }
}

// ---------------------------------------------------------------------------
// LayerNorm (one-pass). Writes fp32 y and optional fp16 yh.
// ---------------------------------------------------------------------------
__device__ __forceinline__ void block_reduce2(float& s, float& s2,
                                              float* sh1, float* sh2,
                                              int lane, int w)
{
#pragma unroll
    for (int o = 16; o > 0; o >>= 1) {
        s  += __shfl_xor_sync(0xffffffffu, s, o);
        s2 += __shfl_xor_sync(0xffffffffu, s2, o);
    }
    if (lane == 0) { sh1[w] = s; sh2[w] = s2; }
    __syncthreads();
    if (w == 0) {
        float a = (lane < 8) ? sh1[lane] : 0.f;
        float b = (lane < 8) ? sh2[lane] : 0.f;
#pragma unroll
        for (int o = 4; o > 0; o >>= 1) {
            a += __shfl_xor_sync(0xffffffffu, a, o);
            b += __shfl_xor_sync(0xffffffffu, b, o);
        }
        if (lane == 0) { sh1[0] = a; sh2[0] = b; }
    }
    __syncthreads();
}

__global__ __launch_bounds__(256)
void add_ln_red(const float* __restrict__ x, const float* __restrict__ parts,
                int nparts, const float* __restrict__ bias,
                const float* __restrict__ g, const float* __restrict__ bt,
                float* __restrict__ y, __half* __restrict__ yh)
{
    const int row = blockIdx.x;
    const int t = threadIdx.x;
    const int lane = t & 31, w = t >> 5;
    __shared__ float sh1[8], sh2[8];

    float v[4];
#pragma unroll
    for (int i = 0; i < 4; i++) {
        const int c = t + i * 256;
        const size_t idx = (size_t)row * DD + c;
        float a = parts[idx];
        for (int p = 1; p < nparts; p++) a += parts[(size_t)p * MEG + idx];
        v[i] = x[idx] + a + bias[c];
    }
    float s = 0.f, s2 = 0.f;
#pragma unroll
    for (int i = 0; i < 4; i++) { s += v[i]; s2 += v[i] * v[i]; }
    block_reduce2(s, s2, sh1, sh2, lane, w);
    const float mean = sh1[0] * (1.0f / DD);
    const float var  = sh2[0] * (1.0f / DD) - mean * mean;
    const float inv  = rsqrtf(var + EPSF);

    float r[4];
#pragma unroll
    for (int i = 0; i < 4; i++) {
        const int c = t + i * 256;
        r[i] = g[c] * (v[i] - mean) * inv + bt[c];
        y[(size_t)row * DD + c] = r[i];
    }
    if (yh) {
#pragma unroll
        for (int i = 0; i < 4; i++)
            yh[(size_t)row * DD + t + i * 256] = __float2half_rn(r[i]);
    }
}

__global__ __launch_bounds__(256)
void ln_plain(const float* __restrict__ x, const float* __restrict__ g,
              const float* __restrict__ bt, float* __restrict__ y,
              __half* __restrict__ yh)
{
    const int row = blockIdx.x;
    const int t = threadIdx.x;
    const int lane = t & 31, w = t >> 5;
    __shared__ float sh1[8], sh2[8];

    float v[4];
#pragma unroll
    for (int i = 0; i < 4; i++)
        v[i] = x[(size_t)row * DD + t + i * 256];
    float s = 0.f, s2 = 0.f;
#pragma unroll
    for (int i = 0; i < 4; i++) { s += v[i]; s2 += v[i] * v[i]; }
    block_reduce2(s, s2, sh1, sh2, lane, w);
    const float mean = sh1[0] * (1.0f / DD);
    const float var  = sh2[0] * (1.0f / DD) - mean * mean;
    const float inv  = rsqrtf(var + EPSF);

    float r[4];
#pragma unroll
    for (int i = 0; i < 4; i++) {
        const int c = t + i * 256;
        r[i] = g[c] * (v[i] - mean) * inv + bt[c];
        y[(size_t)row * DD + c] = r[i];
    }
    if (yh) {
#pragma unroll
        for (int i = 0; i < 4; i++)
            yh[(size_t)row * DD + t + i * 256] = __float2half_rn(r[i]);
    }
}

// ---------------------------------------------------------------------------
// Fused attention: scores + mask + softmax + ctx. 32 q-rows per CTA.
// Grid (S/32, B*H), 256 threads, ~80 KB dyn smem (2 CTAs/SM).
// Phase 1: S = Q.K^T (8 warps: qslot = w>>2 over 2x16 rows, kslot = w&3).
// Softmax writes P fp32 to attn (output) and fp16 to ph (gmem, L2-hot).
// Phase 2: ctx = P.V, re-reading this block's own P rows from ph.
// ---------------------------------------------------------------------------
__global__ __launch_bounds__(256)
void attn_fused_f16(const __half* __restrict__ qf,
                    const __half* __restrict__ kf,
                    const __half* __restrict__ vf,
                    const int* __restrict__ mask,
                    int causal,
                    float* __restrict__ attn,
                    __half* __restrict__ ph,
                    __half* __restrict__ ctxb)
{
    extern __shared__ float smemf[];
    uint32_t* Qs = (uint32_t*)smemf;        // 32*36
    uint32_t* Ks = Qs + 32 * 36;            // 64*36 (= 32*72 in phase 2)
    float* Ssm = smemf + (32 + 64) * 36;    // 32*516

    const int bh = blockIdx.y, b = bh >> 4, h = bh & 15;
    const int q0 = blockIdx.x * 32;
    const int t = threadIdx.x, lane = t & 31, w = t >> 5;
    const int g = lane >> 2, cc = lane & 3;
    const int qslot = w >> 2, kslot = w & 3;

    // ---- Phase 1: S = Q.K^T ----
    {
        const int r = t >> 3, ch = t & 7;
        uint4 v = *(const uint4*)&qf[(size_t)(b * SS + q0 + r) * DD + h * DKK + ch * 8];
        *(uint4*)&Qs[r * 36 + ch * 4] = v;
    }

    int mreg[16];
    if (!causal) {
#pragma unroll
        for (int j = 0; j < 16; j++)
            mreg[j] = mask[(size_t)b * SS + lane + j * 32];
    }

    for (int kt = 0; kt < 8; kt++) {
        __syncthreads();
#pragma unroll
        for (int i = 0; i < 2; i++) {
            const int idx = t + i * 256;
            const int r = idx >> 3, ch = idx & 7;
            uint4 v = *(const uint4*)&kf[(size_t)(b * SS + kt * 64 + r) * DD + h * DKK + ch * 8];
            *(uint4*)&Ks[r * 36 + ch * 4] = v;
        }
        __syncthreads();

        float acc[2][4] = {};
        uint32_t af[4];
#pragma unroll
        for (int ksi = 0; ksi < 4; ksi++) {
            const int kp = ksi * 8 + cc;
            const int mb = qslot * 16;
            af[0] = Qs[(mb + g) * 36 + kp];
            af[1] = Qs[(mb + g + 8) * 36 + kp];
            af[2] = Qs[(mb + g) * 36 + kp + 4];
            af[3] = Qs[(mb + g + 8) * 36 + kp + 4];
#pragma unroll
            for (int nj = 0; nj < 2; nj++) {
                const int nbase = kslot * 16 + nj * 8;
                uint32_t bf[2];
                bf[0] = Ks[(nbase + g) * 36 + kp];
                bf[1] = Ks[(nbase + g) * 36 + kp + 4];
                mma16(acc[nj], af, bf);
            }
        }
#pragma unroll
        for (int nj = 0; nj < 2; nj++) {
            const int colb = kt * 64 + kslot * 16 + nj * 8 + 2 * cc;
            const int rr = qslot * 16 + g;
            *(float2*)&Ssm[rr * 516 + colb]       = make_float2(acc[nj][0], acc[nj][1]);
            *(float2*)&Ssm[(rr + 8) * 516 + colb] = make_float2(acc[nj][2], acc[nj][3]);
        }
    }
    __syncthreads();

    // ---- Softmax (warp w handles rows w*4..w*4+3) ----
    for (int i = 0; i < 4; i++) {
        const int rloc = w * 4 + i;
        const int q = q0 + rloc;
        float vals[16];
        float mx = -1e30f;
#pragma unroll
        for (int j = 0; j < 16; j++) {
            const int col = lane + j * 32;
            float v = Ssm[rloc * 516 + col] * INV_SCALE;
            const int m = causal ? mask[((size_t)b * SS + q) * SS + col] : mreg[j];
            if (m == 0) v = -1e9f;
            vals[j] = v;
            mx = fmaxf(mx, v);
        }
#pragma unroll
        for (int o = 16; o > 0; o >>= 1)
            mx = fmaxf(mx, __shfl_xor_sync(0xffffffffu, mx, o));
        float sum = 0.0f;
#pragma unroll
        for (int j = 0; j < 16; j++) {
            vals[j] = expf(vals[j] - mx);
            sum += vals[j];
        }
#pragma unroll
        for (int o = 16; o > 0; o >>= 1)
            sum += __shfl_xor_sync(0xffffffffu, sum, o);
        const float inv = 1.0f / sum;
        float* dst = attn + ((size_t)bh * SS + q) * SS;
        __half* dsth = ph + ((size_t)bh * SS + q) * SS;
#pragma unroll
        for (int j = 0; j < 16; j++) {
            const float p = vals[j] * inv;
            dst[lane + j * 32] = p;
            dsth[lane + j * 32] = __float2half_rn(p);
        }
    }

    // ---- Phase 2: ctx = P.V (P re-read from ph; own rows, L2-hot) ----
    const int qs2 = w >> 2, ds2 = w & 3;   // 2x16 rows, 4x16 cols
    float acc2[2][4] = {};
    for (int kt = 0; kt < 8; kt++) {
        __syncthreads();
        {   // P chunk: 32 rows x 32 half2 into Qs
            const int r = t >> 3, ch = t & 7;
            uint4 v = *(const uint4*)&ph[((size_t)bh * SS + q0 + r) * SS + kt * 64 + ch * 8];
            *(uint4*)&Qs[r * 36 + ch * 4] = v;
        }
#pragma unroll
        for (int i = 0; i < 2; i++) {   // V chunk: 32 pair-rows x 64 cols into Ks
            const int vr = (t >> 4) + i * 16, vc = (t & 15) * 4;
            uint2 vE = *(const uint2*)&vf[(size_t)(b * SS + kt * 64 + 2 * vr) * DD + h * DKK + vc];
            uint2 vO = *(const uint2*)&vf[(size_t)(b * SS + kt * 64 + 2 * vr + 1) * DD + h * DKK + vc];
            *(uint4*)&Ks[vr * 72 + vc] = permT(vE, vO);
        }
        __syncthreads();

        uint32_t af[4], bf[2];
#pragma unroll
        for (int ksi = 0; ksi < 4; ksi++) {
            const int kp = ksi * 8 + cc;
            const int mb = qs2 * 16;
            af[0] = Qs[(mb + g) * 36 + kp];
            af[1] = Qs[(mb + g + 8) * 36 + kp];
            af[2] = Qs[(mb + g) * 36 + kp + 4];
            af[3] = Qs[(mb + g + 8) * 36 + kp + 4];
#pragma unroll
            for (int nj = 0; nj < 2; nj++) {
                const int nbase = ds2 * 16 + nj * 8;
                bf[0] = Ks[kp * 72 + nbase + g];
                bf[1] = Ks[(kp + 4) * 72 + nbase + g];
                mma16(acc2[nj], af, bf);
            }
        }
    }

    __half* Cp = ctxb + (size_t)b * SS * DD + h * DKK;
#pragma unroll
    for (int nj = 0; nj < 2; nj++) {
        const int c = ds2 * 16 + nj * 8 + 2 * cc;
        const int r = q0 + qs2 * 16 + g;
        *(uint32_t*)&Cp[(size_t)r * DD + c]       = pk(acc2[nj][0], acc2[nj][1]);
        *(uint32_t*)&Cp[(size_t)(r + 8) * DD + c] = pk(acc2[nj][2], acc2[nj][3]);
    }
}

// ---------------------------------------------------------------------------
// Host orchestration
// ---------------------------------------------------------------------------
extern "C" void kernel_launch(void* const* d_in, const int* in_sizes, int n_in,
                              void* d_out, int out_size)
{
    const float* src     = (const float*)d_in[0];
    const float* tgt     = (const float*)d_in[1];
    const float* enc_W   = (const float*)d_in[2];
    const float* enc_b   = (const float*)d_in[3];
    const float* enc_W1  = (const float*)d_in[4];
    const float* enc_b1  = (const float*)d_in[5];
    const float* enc_W2  = (const float*)d_in[6];
    const float* enc_b2  = (const float*)d_in[7];
    const float* enc_lng = (const float*)d_in[8];
    const float* enc_lnb = (const float*)d_in[9];
    const float* enc_fg  = (const float*)d_in[10];
    const float* enc_fb  = (const float*)d_in[11];
    const float* dsW     = (const float*)d_in[12];
    const float* dsb     = (const float*)d_in[13];
    const float* dcW     = (const float*)d_in[14];
    const float* dcb     = (const float*)d_in[15];
    const float* dW1     = (const float*)d_in[16];
    const float* db1     = (const float*)d_in[17];
    const float* dW2     = (const float*)d_in[18];
    const float* db2     = (const float*)d_in[19];
    const float* dlng    = (const float*)d_in[20];
    const float* dlnb    = (const float*)d_in[21];
    const float* dfg     = (const float*)d_in[22];
    const float* dfb     = (const float*)d_in[23];
    const int*   src_mask = (const int*)d_in[24];
    const int*   tgt_mask = (const int*)d_in[25];
    float* out = (float*)d_out;

    float* scratch = nullptr;
    cudaGetSymbolAddress((void**)&scratch, g_scratch);

    float*  X    = scratch + 0 * MEG;
    float*  X2   = scratch + 1 * MEG;
    __half* Qh   = (__half*)(scratch + 2 * MEG);   // Q,K,V: 3M halves
    __half* H1h  = (__half*)(scratch + 4 * MEG);   // 4M halves
    __half* Xh   = (__half*)(scratch + 6 * MEG);
    __half* X2h  = (__half*)(scratch + 7 * MEG);
    __half* srch = (__half*)(scratch + 8 * MEG);
    __half* tgth = (__half*)(scratch + 9 * MEG);
    __half* ENCh = (__half*)(scratch + 10 * MEG);
    float*  ATT  = scratch + 11 * MEG;             // 8M floats (fallback)
    float*  ENC  = scratch + 19 * MEG;
    float*  PRT  = scratch + 20 * MEG;             // 4M floats
    __half* CKh  = (__half*)(scratch + 24 * MEG);  // 4M halves
    __half* CVh  = (__half*)(scratch + 26 * MEG);  // 4M halves
    __half* WH   = (__half*)(scratch + 28 * MEG);  // 112M halves
    __half* Ph   = (__half*)(scratch + 84 * MEG);  // 8.4M halves (P fp16)

    const size_t M1 = MEG;
    __half* encWt = WH;                 // [L*4][1024][1024]
    __half* dsWt  = WH + 16 * M1;
    __half* dcWt  = WH + 32 * M1;
    __half* eW1t  = WH + 48 * M1;       // [L][4096][1024]
    __half* eW2t  = WH + 64 * M1;       // [L][1024][4096]
    __half* dW1t  = WH + 80 * M1;
    __half* dW2t  = WH + 96 * M1;

    const size_t SLAB      = (size_t)BB * HH * SS * SS;
    const size_t OFF_ENC   = (size_t)BB * SS * DD;
    const size_t OFF_SELF  = OFF_ENC + (size_t)LL * SLAB;
    const size_t OFF_CROSS = OFF_SELF + (size_t)LL * SLAB;
    const size_t TOTAL     = OFF_CROSS + (size_t)LL * SLAB;
    const bool full = ((size_t)out_size >= TOTAL);

    const int SM_W = 4 * (64 * 20 + 128 * 20) * 4;  // 61440 B
    cudaFuncSetAttribute(gemm_wide_h, cudaFuncAttributeMaxDynamicSharedMemorySize, SM_W);
    const size_t SC_SMEM = (size_t)((32 + 64) * 36 + 32 * 516) * sizeof(float);
    cudaFuncSetAttribute(attn_fused_f16,
                         cudaFuncAttributeMaxDynamicSharedMemorySize, (int)SC_SMEM);

    // ---------------- Prepass ----------------
    cvt16<<<1024, 256>>>(src, srch, MROWS * DD);
    cvt16<<<1024, 256>>>(tgt, tgth, MROWS * DD);
    tcvt<<<dim3(32, 32, 16), 256>>>(enc_W, encWt, 1024, 1024);
    tcvt<<<dim3(32, 32, 16), 256>>>(dsW, dsWt, 1024, 1024);
    tcvt<<<dim3(32, 32, 16), 256>>>(dcW, dcWt, 1024, 1024);
    tcvt<<<dim3(128, 32, 4), 256>>>(enc_W1, eW1t, 1024, 4096);
    tcvt<<<dim3(32, 128, 4), 256>>>(enc_W2, eW2t, 4096, 1024);
    tcvt<<<dim3(128, 32, 4), 256>>>(dW1, dW1t, 1024, 4096);
    tcvt<<<dim3(32, 128, 4), 256>>>(dW2, dW2t, 4096, 1024);

    dim3 gQKV(3072 / 128, MROWS / 64);   // 384 CTAs
    dim3 gKVB(4096 / 128, MROWS / 64);   // 512 CTAs
    dim3 gF1(DFFF / 128, MROWS / 64);    // 512 CTAs
    dim3 g64(16, 16);                    // 256 CTAs
    dim3 gSK2(16, 16, 2);
    dim3 gSK4(16, 16, 4);
    dim3 gS(SS / 32, BB * HH);           // 512 CTAs

    // ------------------------- Encoder -------------------------
    const float* cur = src;
    const __half* curh = srch;
    for (int l = 0; l < LL; l++) {
        const float* bb = enc_b + (size_t)l * 4 * DD;
        gemm_wide_h<<<gQKV, 256, SM_W>>>(curh, encWt + (size_t)l * 4 * M1, bb, Qh,
                                         DD, DD, 0, (long long)M1, DD, (long long)M1);
        float* adst = full ? out + OFF_ENC + (size_t)l * SLAB : ATT;
        attn_fused_f16<<<gS, 256, SC_SMEM>>>(Qh, Qh + M1, Qh + 2 * M1, src_mask, 0,
                                             adst, Ph, Qh);
        gemm_sk_h<<<gSK2, 128>>>(Qh, encWt + ((size_t)l * 4 + 3) * M1, PRT, 1024, 1024, 512);
        add_ln_red<<<MROWS, 256>>>(cur, PRT, 2, bb + 3 * DD,
                                   enc_lng + (size_t)l * 2 * DD,
                                   enc_lnb + (size_t)l * 2 * DD, X2, X2h);
        gemm_wide_h<<<gF1, 256, SM_W>>>(X2h, eW1t + (size_t)l * 4 * M1,
                                        enc_b1 + (size_t)l * DFFF, H1h,
                                        DD, DFFF, 1, 0, 0, 0);
        gemm_sk_h<<<gSK4, 128>>>(H1h, eW2t + (size_t)l * 4 * M1, PRT, 4096, 4096, 1024);
        add_ln_red<<<MROWS, 256>>>(X2, PRT, 4, enc_b2 + (size_t)l * DD,
                                   enc_lng + (size_t)l * 2 * DD + DD,
                                   enc_lnb + (size_t)l * 2 * DD + DD, X, Xh);
        cur = X; curh = Xh;
    }
    ln_plain<<<MROWS, 256>>>(cur, enc_fg, enc_fb, ENC, ENCh);

    // Batched cross-attention K/V (blk = layer)
    gemm_wide_h<<<gKVB, 256, SM_W>>>(ENCh, dcWt + M1, dcb + DD, CKh,
                                     DD, DD, 0, 4LL * M1, 4LL * DD, (long long)M1);
    gemm_wide_h<<<gKVB, 256, SM_W>>>(ENCh, dcWt + 2 * M1, dcb + 2 * DD, CVh,
                                     DD, DD, 0, 4LL * M1, 4LL * DD, (long long)M1);

    // ------------------------- Decoder -------------------------
    cur = tgt; curh = tgth;
    for (int l = 0; l < LL; l++) {
        const float* bs = dsb + (size_t)l * 4 * DD;
        gemm_wide_h<<<gQKV, 256, SM_W>>>(curh, dsWt + (size_t)l * 4 * M1, bs, Qh,
                                         DD, DD, 0, (long long)M1, DD, (long long)M1);
        float* adst = full ? out + OFF_SELF + (size_t)l * SLAB : ATT;
        attn_fused_f16<<<gS, 256, SC_SMEM>>>(Qh, Qh + M1, Qh + 2 * M1, tgt_mask, 1,
                                             adst, Ph, Qh);
        gemm_sk_h<<<gSK2, 128>>>(Qh, dsWt + ((size_t)l * 4 + 3) * M1, PRT, 1024, 1024, 512);
        add_ln_red<<<MROWS, 256>>>(cur, PRT, 2, bs + 3 * DD,
                                   dlng + (size_t)l * 3 * DD,
                                   dlnb + (size_t)l * 3 * DD, X, Xh);

        const float* bc = dcb + (size_t)l * 4 * DD;
        gemm_h64<<<g64, 128>>>(Xh, dcWt + (size_t)l * 4 * M1, bc, Qh);
        adst = full ? out + OFF_CROSS + (size_t)l * SLAB : ATT;
        attn_fused_f16<<<gS, 256, SC_SMEM>>>(Qh, CKh + (size_t)l * M1, CVh + (size_t)l * M1,
                                             src_mask, 0, adst, Ph, Qh);
        gemm_sk_h<<<gSK2, 128>>>(Qh, dcWt + ((size_t)l * 4 + 3) * M1, PRT, 1024, 1024, 512);
        add_ln_red<<<MROWS, 256>>>(X, PRT, 2, bc + 3 * DD,
                                   dlng + (size_t)l * 3 * DD + DD,
                                   dlnb + (size_t)l * 3 * DD + DD, X2, X2h);

        gemm_wide_h<<<gF1, 256, SM_W>>>(X2h, dW1t + (size_t)l * 4 * M1,
                                        db1 + (size_t)l * DFFF, H1h,
                                        DD, DFFF, 1, 0, 0, 0);
        gemm_sk_h<<<gSK4, 128>>>(H1h, dW2t + (size_t)l * 4 * M1, PRT, 4096, 4096, 1024);
        add_ln_red<<<MROWS, 256>>>(X2, PRT, 4, db2 + (size_t)l * DD,
                                   dlng + (size_t)l * 3 * DD + 2 * DD,
                                   dlnb + (size_t)l * 3 * DD + 2 * DD, X, Xh);
        cur = X; curh = Xh;
    }
    ln_plain<<<MROWS, 256>>>(cur, dfg, dfb, out, nullptr);
}

// round 14
// speedup vs baseline: 1.5432x; 1.5432x over previous
#include <cuda_runtime.h>
#include <cuda_fp16.h>
#include <cstdint>
#include <cstddef>

// ---------------------------------------------------------------------------
// Transformer forward, R14: R12 (separate scores/ctx attention — fused variant
// regressed twice and is abandoned) + vectorized float4 LayerNorm kernels.
// ---------------------------------------------------------------------------

#define BB   2
#define SS   512
#define DD   1024
#define HH   16
#define DKK  64
#define DFFF 4096
#define LL   4
#define MROWS (BB*SS)          // 1024
#define EPSF 1e-5f
#define INV_SCALE 0.125f       // 1/sqrt(DK)

static const size_t MEG = 1u << 20;
__device__ __align__(16) float g_scratch[89u * (1u << 20)];   // 356 MB

// ---------------------------------------------------------------------------
// helpers
// ---------------------------------------------------------------------------
__device__ __forceinline__ uint32_t pk(float lo, float hi) {
    __half2 h = __floats2half2_rn(lo, hi);
    return *(uint32_t*)&h;
}
__device__ __forceinline__ uint2 pk4(float4 v) {
    return make_uint2(pk(v.x, v.y), pk(v.z, v.w));
}
__device__ __forceinline__ uint4 permT(uint2 e, uint2 o) {
    uint4 r;
    r.x = __byte_perm(e.x, o.x, 0x5410);
    r.y = __byte_perm(e.x, o.x, 0x7632);
    r.z = __byte_perm(e.y, o.y, 0x5410);
    r.w = __byte_perm(e.y, o.y, 0x7632);
    return r;
}
__device__ __forceinline__ void mma16(float* c, const uint32_t* a, const uint32_t* b) {
    asm volatile(
        "mma.sync.aligned.m16n8k16.row.col.f32.f16.f16.f32 "
        "{%0,%1,%2,%3}, {%4,%5,%6,%7}, {%8,%9}, {%0,%1,%2,%3};\n"
        : "+f"(c[0]), "+f"(c[1]), "+f"(c[2]), "+f"(c[3])
        : "r"(a[0]), "r"(a[1]), "r"(a[2]), "r"(a[3]), "r"(b[0]), "r"(b[1]));
}
__device__ __forceinline__ uint32_t smaddr(const void* p) {
    return (uint32_t)__cvta_generic_to_shared(p);
}
__device__ __forceinline__ void cpa16(uint32_t dsm, const void* gsrc) {
    asm volatile("cp.async.cg.shared.global [%0], [%1], 16;" :: "r"(dsm), "l"(gsrc));
}
#define CP_COMMIT() asm volatile("cp.async.commit_group;")
#define CP_WAIT2()  asm volatile("cp.async.wait_group 2;")

// ---------------------------------------------------------------------------
// Prepass: fp32 -> fp16 convert
// ---------------------------------------------------------------------------
__global__ __launch_bounds__(256)
void cvt16(const float* __restrict__ x, __half* __restrict__ y, int n)
{
    const int i = (blockIdx.x * 256 + threadIdx.x) * 4;
    if (i < n) {
        float4 v = *(const float4*)&x[i];
        *(uint2*)&y[i] = pk4(v);
    }
}

// Batched transpose+convert W[K,N] fp32 -> Wt[N,K] fp16.
__global__ __launch_bounds__(256)
void tcvt(const float* __restrict__ src, __half* __restrict__ dst, int K, int N)
{
    const size_t zoff = (size_t)blockIdx.z * K * N;
    src += zoff; dst += zoff;
    __shared__ float tile[32][33];
    const int t = threadIdx.x;
    const int tx = (t & 7) * 4, ty = t >> 3;
    const int x0 = blockIdx.x * 32, y0 = blockIdx.y * 32;

    float4 v = *(const float4*)&src[(size_t)(y0 + ty) * N + x0 + tx];
    tile[ty][tx] = v.x; tile[ty][tx + 1] = v.y;
    tile[ty][tx + 2] = v.z; tile[ty][tx + 3] = v.w;
    __syncthreads();

    const float a = tile[tx][ty], b = tile[tx + 1][ty];
    const float c = tile[tx + 2][ty], d = tile[tx + 3][ty];
    *(uint2*)&dst[(size_t)(x0 + ty) * K + y0 + tx] = make_uint2(pk(a, b), pk(c, d));
}

// ---------------------------------------------------------------------------
// Wide GEMM: fp16 A[M][K] @ fp16 Wt[N][K] -> fp16 C (+fp32 bias, opt ReLU).
// 64x128 tile, 256 thr, cp.async 4-stage. Dyn smem 61440 B.
// ---------------------------------------------------------------------------
__global__ __launch_bounds__(256, 2)
void gemm_wide_h(const __half* __restrict__ A, const __half* __restrict__ Wt,
                 const float* __restrict__ bias, __half* __restrict__ C,
                 int K, int nb, int relu,
                 long long wstride, long long bstride, long long cstride)
{
    constexpr int ASTR = 20, BSTR = 20;
    constexpr int ASZ = 64 * ASTR, BSZ = 128 * BSTR, STG = ASZ + BSZ;
    extern __shared__ uint32_t smg[];

    const int t = threadIdx.x, lane = t & 31, w = t >> 5;
    const int g = lane >> 2, cc = lane & 3;
    const int wm = w >> 2, wn = w & 3;
    const int row0 = blockIdx.y * 64;
    const int colg = blockIdx.x * 128;
    const int blk  = colg / nb;
    const int col0 = colg - blk * nb;
    const __half* Wp = Wt + (size_t)blk * (size_t)wstride;
    const float* bp = bias + (size_t)blk * (size_t)bstride;
    __half* Cp = C + (size_t)blk * (size_t)cstride;

    const uint32_t sb = smaddr(smg);
    const int arow = t >> 2, ach = t & 3;

    auto issue = [&](int it) {
        const int k0 = it << 5;
        const uint32_t base = sb + (uint32_t)((it & 3) * STG) * 4u;
        cpa16(base + (uint32_t)(arow * ASTR + ach * 4) * 4u,
              A + (size_t)(row0 + arow) * K + k0 + ach * 8);
#pragma unroll
        for (int i = 0; i < 2; i++) {
            const int idx = t + i * 256;
            const int br = idx >> 2, bch = idx & 3;
            cpa16(base + (uint32_t)(ASZ + br * BSTR + bch * 4) * 4u,
                  Wp + (size_t)(col0 + br) * K + k0 + bch * 8);
        }
    };

    float acc[2][4][4] = {};
    const int NK = K >> 5;
    issue(0); CP_COMMIT();
    issue(1); CP_COMMIT();
    issue(2); CP_COMMIT();

    for (int it = 0; it < NK; it++) {
        CP_WAIT2();
        __syncthreads();
        if (it + 3 < NK) issue(it + 3);
        CP_COMMIT();

        const uint32_t* as_ = smg + (it & 3) * STG;
        const uint32_t* bs_ = smg + (it & 3) * STG + ASZ;
        uint32_t af[2][4], bf[4][2];
#pragma unroll
        for (int ksi = 0; ksi < 2; ksi++) {
            const int kp = ksi * 8 + cc;
#pragma unroll
            for (int mi = 0; mi < 2; mi++) {
                const int mb = wm * 32 + mi * 16;
                af[mi][0] = as_[(mb + g) * ASTR + kp];
                af[mi][1] = as_[(mb + g + 8) * ASTR + kp];
                af[mi][2] = as_[(mb + g) * ASTR + kp + 4];
                af[mi][3] = as_[(mb + g + 8) * ASTR + kp + 4];
            }
#pragma unroll
            for (int nj = 0; nj < 4; nj++) {
                const int nrow = wn * 32 + nj * 8 + g;
                bf[nj][0] = bs_[nrow * BSTR + kp];
                bf[nj][1] = bs_[nrow * BSTR + kp + 4];
            }
#pragma unroll
            for (int mi = 0; mi < 2; mi++)
#pragma unroll
                for (int nj = 0; nj < 4; nj++)
                    mma16(acc[mi][nj], af[mi], bf[nj]);
        }
    }

#pragma unroll
    for (int mi = 0; mi < 2; mi++) {
        const int r0 = row0 + wm * 32 + mi * 16 + g;
#pragma unroll
        for (int nj = 0; nj < 4; nj++) {
            const int c = col0 + wn * 32 + nj * 8 + 2 * cc;
            const float b0v = bp[c], b1v = bp[c + 1];
            float v0 = acc[mi][nj][0] + b0v, v1 = acc[mi][nj][1] + b1v;
            float v2 = acc[mi][nj][2] + b0v, v3 = acc[mi][nj][3] + b1v;
            if (relu) {
                v0 = fmaxf(v0, 0.f); v1 = fmaxf(v1, 0.f);
                v2 = fmaxf(v2, 0.f); v3 = fmaxf(v3, 0.f);
            }
            *(uint32_t*)&Cp[(size_t)r0 * nb + c]       = pk(v0, v1);
            *(uint32_t*)&Cp[(size_t)(r0 + 8) * nb + c] = pk(v2, v3);
        }
    }
}

// ---------------------------------------------------------------------------
// 128-thread 64x64 cp.async core (fp16 A, fp16 Wt rows).
// ---------------------------------------------------------------------------
#define GEMMH64_CORE(AP, WP, LDA, LDW, NKV)                                     \
    constexpr int ASTR = 20, BSTR = 20;                                         \
    constexpr int ASZ = 64 * ASTR, BSZ = 64 * BSTR, STG = ASZ + BSZ;            \
    __shared__ uint32_t smg[4 * STG];                                           \
    const int t = threadIdx.x, lane = t & 31, w = t >> 5;                       \
    const int g = lane >> 2, cc = lane & 3;                                     \
    const int wm = w >> 1, wn = w & 1;                                          \
    const int row0 = blockIdx.y * 64;                                           \
    const int col0 = blockIdx.x * 64;                                           \
    const uint32_t sb = smaddr(smg);                                            \
    auto issue = [&](int it) {                                                  \
        const int k0 = it << 5;                                                 \
        const uint32_t base = sb + (uint32_t)((it & 3) * STG) * 4u;             \
        _Pragma("unroll")                                                       \
        for (int i = 0; i < 2; i++) {                                           \
            const int idx = t + i * 128;                                        \
            const int r = idx >> 2, ch = idx & 3;                               \
            cpa16(base + (uint32_t)(r * ASTR + ch * 4) * 4u,                    \
                  AP + (size_t)(row0 + r) * LDA + k0 + ch * 8);                 \
            cpa16(base + (uint32_t)(ASZ + r * BSTR + ch * 4) * 4u,              \
                  WP + (size_t)(col0 + r) * LDW + k0 + ch * 8);                 \
        }                                                                       \
    };                                                                          \
    float acc[2][4][4] = {};                                                    \
    const int NK = (NKV);                                                       \
    issue(0); CP_COMMIT();                                                      \
    issue(1); CP_COMMIT();                                                      \
    issue(2); CP_COMMIT();                                                      \
    for (int it = 0; it < NK; it++) {                                           \
        CP_WAIT2();                                                             \
        __syncthreads();                                                        \
        if (it + 3 < NK) issue(it + 3);                                         \
        CP_COMMIT();                                                            \
        const uint32_t* as_ = smg + (it & 3) * STG;                             \
        const uint32_t* bs_ = smg + (it & 3) * STG + ASZ;                       \
        uint32_t af[2][4], bf[4][2];                                            \
        _Pragma("unroll")                                                       \
        for (int ksi = 0; ksi < 2; ksi++) {                                     \
            const int kp = ksi * 8 + cc;                                        \
            _Pragma("unroll")                                                   \
            for (int mi = 0; mi < 2; mi++) {                                    \
                const int mb = wm * 32 + mi * 16;                               \
                af[mi][0] = as_[(mb + g) * ASTR + kp];                          \
                af[mi][1] = as_[(mb + g + 8) * ASTR + kp];                      \
                af[mi][2] = as_[(mb + g) * ASTR + kp + 4];                      \
                af[mi][3] = as_[(mb + g + 8) * ASTR + kp + 4];                  \
            }                                                                   \
            _Pragma("unroll")                                                   \
            for (int nj = 0; nj < 4; nj++) {                                    \
                const int nrow = wn * 32 + nj * 8 + g;                          \
                bf[nj][0] = bs_[nrow * BSTR + kp];                              \
                bf[nj][1] = bs_[nrow * BSTR + kp + 4];                          \
            }                                                                   \
            _Pragma("unroll")                                                   \
            for (int mi = 0; mi < 2; mi++)                                      \
                _Pragma("unroll")                                               \
                for (int nj = 0; nj < 4; nj++)                                  \
                    mma16(acc[mi][nj], af[mi], bf[nj]);                         \
        }                                                                       \
    }

// cross-Q: fp16 A @ Wt + bias -> fp16 C.
__global__ __launch_bounds__(128, 4)
void gemm_h64(const __half* __restrict__ A, const __half* __restrict__ Wt,
              const float* __restrict__ bias, __half* __restrict__ C)
{
    GEMMH64_CORE(A, Wt, 1024, 1024, 32)
#pragma unroll
    for (int mi = 0; mi < 2; mi++) {
        const int r0 = row0 + wm * 32 + mi * 16 + g;
#pragma unroll
        for (int nj = 0; nj < 4; nj++) {
            const int c = col0 + wn * 32 + nj * 8 + 2 * cc;
            const float b0v = bias[c], b1v = bias[c + 1];
            *(uint32_t*)&C[(size_t)r0 * 1024 + c] =
                pk(acc[mi][nj][0] + b0v, acc[mi][nj][1] + b1v);
            *(uint32_t*)&C[(size_t)(r0 + 8) * 1024 + c] =
                pk(acc[mi][nj][2] + b0v, acc[mi][nj][3] + b1v);
        }
    }
}

// Split-K: parts[z] = A[:, zKc:(z+1)Kc] @ Wt-cols-slice. Grid (16,16,nsplit).
__global__ __launch_bounds__(128, 4)
void gemm_sk_h(const __half* __restrict__ A, const __half* __restrict__ Wt,
               float* __restrict__ parts, int lda, int ldw, int Kc)
{
    const int z = blockIdx.z;
    const __half* Az = A + (size_t)z * Kc;
    const __half* Wz = Wt + (size_t)z * Kc;
    float* Cp = parts + (size_t)z * MEG;
    GEMMH64_CORE(Az, Wz, lda, ldw, (Kc >> 5))
#pragma unroll
    for (int mi = 0; mi < 2; mi++) {
        const int r0 = row0 + wm * 32 + mi * 16 + g;
#pragma unroll
        for (int nj = 0; nj < 4; nj++) {
            const int c = col0 + wn * 32 + nj * 8 + 2 * cc;
            *(float2*)&Cp[(size_t)r0 * 1024 + c] =
                make_float2(acc[mi][nj][0], acc[mi][nj][1]);
            *(float2*)&Cp[(size_t)(r0 + 8) * 1024 + c] =
                make_float2(acc[mi][nj][2], acc[mi][nj][3]);
        }
    }
}

// ---------------------------------------------------------------------------
// LayerNorm (one-pass, float4 vectorized). Writes fp32 y and optional fp16 yh.
// Thread t handles elements [4t, 4t+4).
// ---------------------------------------------------------------------------
__device__ __forceinline__ void block_reduce2(float& s, float& s2,
                                              float* sh1, float* sh2,
                                              int lane, int w)
{
#pragma unroll
    for (int o = 16; o > 0; o >>= 1) {
        s  += __shfl_xor_sync(0xffffffffu, s, o);
        s2 += __shfl_xor_sync(0xffffffffu, s2, o);
    }
    if (lane == 0) { sh1[w] = s; sh2[w] = s2; }
    __syncthreads();
    if (w == 0) {
        float a = (lane < 8) ? sh1[lane] : 0.f;
        float b = (lane < 8) ? sh2[lane] : 0.f;
#pragma unroll
        for (int o = 4; o > 0; o >>= 1) {
            a += __shfl_xor_sync(0xffffffffu, a, o);
            b += __shfl_xor_sync(0xffffffffu, b, o);
        }
        if (lane == 0) { sh1[0] = a; sh2[0] = b; }
    }
    __syncthreads();
}

__global__ __launch_bounds__(256)
void add_ln_red(const float* __restrict__ x, const float* __restrict__ parts,
                int nparts, const float* __restrict__ bias,
                const float* __restrict__ g, const float* __restrict__ bt,
                float* __restrict__ y, __half* __restrict__ yh)
{
    const int row = blockIdx.x;
    const int t = threadIdx.x;
    const int lane = t & 31, w = t >> 5;
    __shared__ float sh1[8], sh2[8];

    const int c = t * 4;
    const size_t idx = (size_t)row * DD + c;
    float4 v  = *(const float4*)&x[idx];
    float4 bv = *(const float4*)&bias[c];
    v.x += bv.x; v.y += bv.y; v.z += bv.z; v.w += bv.w;
    for (int p = 0; p < nparts; p++) {
        float4 q = *(const float4*)&parts[(size_t)p * MEG + idx];
        v.x += q.x; v.y += q.y; v.z += q.z; v.w += q.w;
    }
    float s  = v.x + v.y + v.z + v.w;
    float s2 = v.x * v.x + v.y * v.y + v.z * v.z + v.w * v.w;
    block_reduce2(s, s2, sh1, sh2, lane, w);
    const float mean = sh1[0] * (1.0f / DD);
    const float var  = sh2[0] * (1.0f / DD) - mean * mean;
    const float inv  = rsqrtf(var + EPSF);

    float4 gv = *(const float4*)&g[c];
    float4 tv = *(const float4*)&bt[c];
    float4 r;
    r.x = gv.x * (v.x - mean) * inv + tv.x;
    r.y = gv.y * (v.y - mean) * inv + tv.y;
    r.z = gv.z * (v.z - mean) * inv + tv.z;
    r.w = gv.w * (v.w - mean) * inv + tv.w;
    *(float4*)&y[idx] = r;
    if (yh) *(uint2*)&yh[idx] = pk4(r);
}

__global__ __launch_bounds__(256)
void ln_plain(const float* __restrict__ x, const float* __restrict__ g,
              const float* __restrict__ bt, float* __restrict__ y,
              __half* __restrict__ yh)
{
    const int row = blockIdx.x;
    const int t = threadIdx.x;
    const int lane = t & 31, w = t >> 5;
    __shared__ float sh1[8], sh2[8];

    const int c = t * 4;
    const size_t idx = (size_t)row * DD + c;
    float4 v = *(const float4*)&x[idx];
    float s  = v.x + v.y + v.z + v.w;
    float s2 = v.x * v.x + v.y * v.y + v.z * v.z + v.w * v.w;
    block_reduce2(s, s2, sh1, sh2, lane, w);
    const float mean = sh1[0] * (1.0f / DD);
    const float var  = sh2[0] * (1.0f / DD) - mean * mean;
    const float inv  = rsqrtf(var + EPSF);

    float4 gv = *(const float4*)&g[c];
    float4 tv = *(const float4*)&bt[c];
    float4 r;
    r.x = gv.x * (v.x - mean) * inv + tv.x;
    r.y = gv.y * (v.y - mean) * inv + tv.y;
    r.z = gv.z * (v.z - mean) * inv + tv.z;
    r.w = gv.w * (v.w - mean) * inv + tv.w;
    *(float4*)&y[idx] = r;
    if (yh) *(uint2*)&yh[idx] = pk4(r);
}

// ---------------------------------------------------------------------------
// Scores + mask + softmax. 32 q-rows per CTA (512 CTAs, ~80 KB smem).
// Writes P fp32 to attn (output) and fp16 to ph (feeds ctx).
// ---------------------------------------------------------------------------
__global__ __launch_bounds__(256)
void attn_scores_f16(const __half* __restrict__ qf,
                     const __half* __restrict__ kf,
                     const int* __restrict__ mask,
                     int causal,
                     float* __restrict__ attn,
                     __half* __restrict__ ph)
{
    extern __shared__ float smemf[];
    uint32_t* Qs = (uint32_t*)smemf;        // 32*36
    uint32_t* Ks = Qs + 32 * 36;            // 64*36
    float* Ssm = smemf + (32 + 64) * 36;    // 32*516

    const int bh = blockIdx.y, b = bh >> 4, h = bh & 15;
    const int q0 = blockIdx.x * 32;
    const int t = threadIdx.x, lane = t & 31, w = t >> 5;
    const int g = lane >> 2, cc = lane & 3;
    const int qslot = w >> 2, kslot = w & 3;

    {
        const int r = t >> 3, ch = t & 7;
        uint4 v = *(const uint4*)&qf[(size_t)(b * SS + q0 + r) * DD + h * DKK + ch * 8];
        *(uint4*)&Qs[r * 36 + ch * 4] = v;
    }

    int mreg[16];
    if (!causal) {
#pragma unroll
        for (int j = 0; j < 16; j++)
            mreg[j] = mask[(size_t)b * SS + lane + j * 32];
    }

    for (int kt = 0; kt < 8; kt++) {
        __syncthreads();
#pragma unroll
        for (int i = 0; i < 2; i++) {
            const int idx = t + i * 256;
            const int r = idx >> 3, ch = idx & 7;
            uint4 v = *(const uint4*)&kf[(size_t)(b * SS + kt * 64 + r) * DD + h * DKK + ch * 8];
            *(uint4*)&Ks[r * 36 + ch * 4] = v;
        }
        __syncthreads();

        float acc[2][4] = {};
        uint32_t af[4];
#pragma unroll
        for (int ksi = 0; ksi < 4; ksi++) {
            const int kp = ksi * 8 + cc;
            const int mb = qslot * 16;
            af[0] = Qs[(mb + g) * 36 + kp];
            af[1] = Qs[(mb + g + 8) * 36 + kp];
            af[2] = Qs[(mb + g) * 36 + kp + 4];
            af[3] = Qs[(mb + g + 8) * 36 + kp + 4];
#pragma unroll
            for (int nj = 0; nj < 2; nj++) {
                const int nbase = kslot * 16 + nj * 8;
                uint32_t bf[2];
                bf[0] = Ks[(nbase + g) * 36 + kp];
                bf[1] = Ks[(nbase + g) * 36 + kp + 4];
                mma16(acc[nj], af, bf);
            }
        }
#pragma unroll
        for (int nj = 0; nj < 2; nj++) {
            const int colb = kt * 64 + kslot * 16 + nj * 8 + 2 * cc;
            const int rr = qslot * 16 + g;
            *(float2*)&Ssm[rr * 516 + colb]       = make_float2(acc[nj][0], acc[nj][1]);
            *(float2*)&Ssm[(rr + 8) * 516 + colb] = make_float2(acc[nj][2], acc[nj][3]);
        }
    }
    __syncthreads();

    for (int i = 0; i < 4; i++) {
        const int rloc = w * 4 + i;
        const int q = q0 + rloc;
        float vals[16];
        float mx = -1e30f;
#pragma unroll
        for (int j = 0; j < 16; j++) {
            const int col = lane + j * 32;
            float v = Ssm[rloc * 516 + col] * INV_SCALE;
            const int m = causal ? mask[((size_t)b * SS + q) * SS + col] : mreg[j];
            if (m == 0) v = -1e9f;
            vals[j] = v;
            mx = fmaxf(mx, v);
        }
#pragma unroll
        for (int o = 16; o > 0; o >>= 1)
            mx = fmaxf(mx, __shfl_xor_sync(0xffffffffu, mx, o));
        float sum = 0.0f;
#pragma unroll
        for (int j = 0; j < 16; j++) {
            vals[j] = expf(vals[j] - mx);
            sum += vals[j];
        }
#pragma unroll
        for (int o = 16; o > 0; o >>= 1)
            sum += __shfl_xor_sync(0xffffffffu, sum, o);
        const float inv = 1.0f / sum;
        float* dst = attn + ((size_t)bh * SS + q) * SS;
        __half* dsth = ph + ((size_t)bh * SS + q) * SS;
#pragma unroll
        for (int j = 0; j < 16; j++) {
            const float p = vals[j] * inv;
            dst[lane + j * 32] = p;
            dsth[lane + j * 32] = __float2half_rn(p);
        }
    }
}

// ---------------------------------------------------------------------------
// Context: P fp16 @ V fp16 -> ctx fp16. Double-buffered K-step 32.
// ---------------------------------------------------------------------------
__global__ __launch_bounds__(256)
void attn_ctx_f16(const __half* __restrict__ ph,
                  const __half* __restrict__ vf,
                  __half* __restrict__ ctx)
{
    constexpr int ASTR = 20, BSTR = 72;
    constexpr int ASZ = 64 * ASTR, BSZ = 16 * BSTR, STG = ASZ + BSZ;
    __shared__ uint32_t smg[2 * STG];

    const int bh = blockIdx.y, b = bh >> 4, h = bh & 15;
    const int q0 = blockIdx.x * 64;
    const int t = threadIdx.x, lane = t & 31, w = t >> 5;
    const int g = lane >> 2, cc = lane & 3;
    const int qslot = w & 3, dslot = w >> 2;
    const __half* Ap = ph + (size_t)bh * SS * SS;
    const __half* Vp = vf + (size_t)b * SS * DD + h * DKK;

    const int ar = t >> 3, ac = (t & 7) << 2;
    const int vr = t >> 4, vc = (t & 15) << 2;

    uint2 aR[2], vE, vO;
    auto loadAB = [&](int k0) {
#pragma unroll
        for (int i = 0; i < 2; i++)
            aR[i] = *(const uint2*)&Ap[(size_t)(q0 + ar + i * 32) * SS + k0 + ac];
        vE = *(const uint2*)&Vp[(size_t)(k0 + 2 * vr) * DD + vc];
        vO = *(const uint2*)&Vp[(size_t)(k0 + 2 * vr + 1) * DD + vc];
    };
    auto storeAB = [&](int p) {
        uint32_t* as_ = smg + p * STG;
        uint32_t* bs_ = smg + p * STG + ASZ;
#pragma unroll
        for (int i = 0; i < 2; i++)
            *(uint2*)&as_[(ar + i * 32) * ASTR + (ac >> 1)] = aR[i];
        *(uint4*)&bs_[vr * BSTR + vc] = permT(vE, vO);
    };

    float acc[4][4] = {};
    const int NK = 16;
    loadAB(0);
    storeAB(0);
    loadAB(32);
    __syncthreads();

    for (int it = 0; it < NK; it++) {
        const int p = it & 1;
        if (it + 1 < NK) storeAB(p ^ 1);
        if (it + 2 < NK) loadAB((it + 2) << 5);

        const uint32_t* as_ = smg + p * STG;
        const uint32_t* bs_ = smg + p * STG + ASZ;
        uint32_t af[4], bf[2];
#pragma unroll
        for (int ksi = 0; ksi < 2; ksi++) {
            const int kp = ksi * 8 + cc;
            const int mb = qslot * 16;
            af[0] = as_[(mb + g) * ASTR + kp];
            af[1] = as_[(mb + g + 8) * ASTR + kp];
            af[2] = as_[(mb + g) * ASTR + kp + 4];
            af[3] = as_[(mb + g + 8) * ASTR + kp + 4];
#pragma unroll
            for (int nj = 0; nj < 4; nj++) {
                const int nbase = dslot * 32 + nj * 8;
                bf[0] = bs_[kp * BSTR + nbase + g];
                bf[1] = bs_[(kp + 4) * BSTR + nbase + g];
                mma16(acc[nj], af, bf);
            }
        }
        __syncthreads();
    }

    __half* Cp = ctx + (size_t)b * SS * DD + h * DKK;
#pragma unroll
    for (int nj = 0; nj < 4; nj++) {
        const int c = dslot * 32 + nj * 8 + 2 * cc;
        const int r = q0 + qslot * 16 + g;
        *(uint32_t*)&Cp[(size_t)r * DD + c]       = pk(acc[nj][0], acc[nj][1]);
        *(uint32_t*)&Cp[(size_t)(r + 8) * DD + c] = pk(acc[nj][2], acc[nj][3]);
    }
}

// ---------------------------------------------------------------------------
// Host orchestration
// ---------------------------------------------------------------------------
extern "C" void kernel_launch(void* const* d_in, const int* in_sizes, int n_in,
                              void* d_out, int out_size)
{
    const float* src     = (const float*)d_in[0];
    const float* tgt     = (const float*)d_in[1];
    const float* enc_W   = (const float*)d_in[2];
    const float* enc_b   = (const float*)d_in[3];
    const float* enc_W1  = (const float*)d_in[4];
    const float* enc_b1  = (const float*)d_in[5];
    const float* enc_W2  = (const float*)d_in[6];
    const float* enc_b2  = (const float*)d_in[7];
    const float* enc_lng = (const float*)d_in[8];
    const float* enc_lnb = (const float*)d_in[9];
    const float* enc_fg  = (const float*)d_in[10];
    const float* enc_fb  = (const float*)d_in[11];
    const float* dsW     = (const float*)d_in[12];
    const float* dsb     = (const float*)d_in[13];
    const float* dcW     = (const float*)d_in[14];
    const float* dcb     = (const float*)d_in[15];
    const float* dW1     = (const float*)d_in[16];
    const float* db1     = (const float*)d_in[17];
    const float* dW2     = (const float*)d_in[18];
    const float* db2     = (const float*)d_in[19];
    const float* dlng    = (const float*)d_in[20];
    const float* dlnb    = (const float*)d_in[21];
    const float* dfg     = (const float*)d_in[22];
    const float* dfb     = (const float*)d_in[23];
    const int*   src_mask = (const int*)d_in[24];
    const int*   tgt_mask = (const int*)d_in[25];
    float* out = (float*)d_out;

    float* scratch = nullptr;
    cudaGetSymbolAddress((void**)&scratch, g_scratch);

    float*  X    = scratch + 0 * MEG;
    float*  X2   = scratch + 1 * MEG;
    __half* Qh   = (__half*)(scratch + 2 * MEG);   // Q,K,V: 3M halves
    __half* H1h  = (__half*)(scratch + 4 * MEG);   // 4M halves
    __half* Xh   = (__half*)(scratch + 6 * MEG);
    __half* X2h  = (__half*)(scratch + 7 * MEG);
    __half* srch = (__half*)(scratch + 8 * MEG);
    __half* tgth = (__half*)(scratch + 9 * MEG);
    __half* ENCh = (__half*)(scratch + 10 * MEG);
    float*  ATT  = scratch + 11 * MEG;             // 8M floats (fallback)
    float*  ENC  = scratch + 19 * MEG;
    float*  PRT  = scratch + 20 * MEG;             // 4M floats
    __half* CKh  = (__half*)(scratch + 24 * MEG);  // 4M halves
    __half* CVh  = (__half*)(scratch + 26 * MEG);  // 4M halves
    __half* WH   = (__half*)(scratch + 28 * MEG);  // 112M halves
    __half* Ph   = (__half*)(scratch + 84 * MEG);  // 8.4M halves (P fp16)

    const size_t M1 = MEG;
    __half* encWt = WH;                 // [L*4][1024][1024]
    __half* dsWt  = WH + 16 * M1;
    __half* dcWt  = WH + 32 * M1;
    __half* eW1t  = WH + 48 * M1;       // [L][4096][1024]
    __half* eW2t  = WH + 64 * M1;       // [L][1024][4096]
    __half* dW1t  = WH + 80 * M1;
    __half* dW2t  = WH + 96 * M1;

    const size_t SLAB      = (size_t)BB * HH * SS * SS;
    const size_t OFF_ENC   = (size_t)BB * SS * DD;
    const size_t OFF_SELF  = OFF_ENC + (size_t)LL * SLAB;
    const size_t OFF_CROSS = OFF_SELF + (size_t)LL * SLAB;
    const size_t TOTAL     = OFF_CROSS + (size_t)LL * SLAB;
    const bool full = ((size_t)out_size >= TOTAL);

    const int SM_W = 4 * (64 * 20 + 128 * 20) * 4;  // 61440 B
    cudaFuncSetAttribute(gemm_wide_h, cudaFuncAttributeMaxDynamicSharedMemorySize, SM_W);
    const size_t SC_SMEM = (size_t)((32 + 64) * 36 + 32 * 516) * sizeof(float);
    cudaFuncSetAttribute(attn_scores_f16,
                         cudaFuncAttributeMaxDynamicSharedMemorySize, (int)SC_SMEM);

    // ---------------- Prepass ----------------
    cvt16<<<1024, 256>>>(src, srch, MROWS * DD);
    cvt16<<<1024, 256>>>(tgt, tgth, MROWS * DD);
    tcvt<<<dim3(32, 32, 16), 256>>>(enc_W, encWt, 1024, 1024);
    tcvt<<<dim3(32, 32, 16), 256>>>(dsW, dsWt, 1024, 1024);
    tcvt<<<dim3(32, 32, 16), 256>>>(dcW, dcWt, 1024, 1024);
    tcvt<<<dim3(128, 32, 4), 256>>>(enc_W1, eW1t, 1024, 4096);
    tcvt<<<dim3(32, 128, 4), 256>>>(enc_W2, eW2t, 4096, 1024);
    tcvt<<<dim3(128, 32, 4), 256>>>(dW1, dW1t, 1024, 4096);
    tcvt<<<dim3(32, 128, 4), 256>>>(dW2, dW2t, 4096, 1024);

    dim3 gQKV(3072 / 128, MROWS / 64);   // 384 CTAs
    dim3 gKVB(4096 / 128, MROWS / 64);   // 512 CTAs
    dim3 gF1(DFFF / 128, MROWS / 64);    // 512 CTAs
    dim3 g64(16, 16);                    // 256 CTAs
    dim3 gSK2(16, 16, 2);
    dim3 gSK4(16, 16, 4);
    dim3 gS(SS / 32, BB * HH);           // 512 CTAs
    dim3 gC(SS / 64, BB * HH);

    // ------------------------- Encoder -------------------------
    const float* cur = src;
    const __half* curh = srch;
    for (int l = 0; l < LL; l++) {
        const float* bb = enc_b + (size_t)l * 4 * DD;
        gemm_wide_h<<<gQKV, 256, SM_W>>>(curh, encWt + (size_t)l * 4 * M1, bb, Qh,
                                         DD, DD, 0, (long long)M1, DD, (long long)M1);
        float* adst = full ? out + OFF_ENC + (size_t)l * SLAB : ATT;
        attn_scores_f16<<<gS, 256, SC_SMEM>>>(Qh, Qh + M1, src_mask, 0, adst, Ph);
        attn_ctx_f16<<<gC, 256>>>(Ph, Qh + 2 * M1, Qh);
        gemm_sk_h<<<gSK2, 128>>>(Qh, encWt + ((size_t)l * 4 + 3) * M1, PRT, 1024, 1024, 512);
        add_ln_red<<<MROWS, 256>>>(cur, PRT, 2, bb + 3 * DD,
                                   enc_lng + (size_t)l * 2 * DD,
                                   enc_lnb + (size_t)l * 2 * DD, X2, X2h);
        gemm_wide_h<<<gF1, 256, SM_W>>>(X2h, eW1t + (size_t)l * 4 * M1,
                                        enc_b1 + (size_t)l * DFFF, H1h,
                                        DD, DFFF, 1, 0, 0, 0);
        gemm_sk_h<<<gSK4, 128>>>(H1h, eW2t + (size_t)l * 4 * M1, PRT, 4096, 4096, 1024);
        add_ln_red<<<MROWS, 256>>>(X2, PRT, 4, enc_b2 + (size_t)l * DD,
                                   enc_lng + (size_t)l * 2 * DD + DD,
                                   enc_lnb + (size_t)l * 2 * DD + DD, X, Xh);
        cur = X; curh = Xh;
    }
    ln_plain<<<MROWS, 256>>>(cur, enc_fg, enc_fb, ENC, ENCh);

    // Batched cross-attention K/V (blk = layer)
    gemm_wide_h<<<gKVB, 256, SM_W>>>(ENCh, dcWt + M1, dcb + DD, CKh,
                                     DD, DD, 0, 4LL * M1, 4LL * DD, (long long)M1);
    gemm_wide_h<<<gKVB, 256, SM_W>>>(ENCh, dcWt + 2 * M1, dcb + 2 * DD, CVh,
                                     DD, DD, 0, 4LL * M1, 4LL * DD, (long long)M1);

    // ------------------------- Decoder -------------------------
    cur = tgt; curh = tgth;
    for (int l = 0; l < LL; l++) {
        const float* bs = dsb + (size_t)l * 4 * DD;
        gemm_wide_h<<<gQKV, 256, SM_W>>>(curh, dsWt + (size_t)l * 4 * M1, bs, Qh,
                                         DD, DD, 0, (long long)M1, DD, (long long)M1);
        float* adst = full ? out + OFF_SELF + (size_t)l * SLAB : ATT;
        attn_scores_f16<<<gS, 256, SC_SMEM>>>(Qh, Qh + M1, tgt_mask, 1, adst, Ph);
        attn_ctx_f16<<<gC, 256>>>(Ph, Qh + 2 * M1, Qh);
        gemm_sk_h<<<gSK2, 128>>>(Qh, dsWt + ((size_t)l * 4 + 3) * M1, PRT, 1024, 1024, 512);
        add_ln_red<<<MROWS, 256>>>(cur, PRT, 2, bs + 3 * DD,
                                   dlng + (size_t)l * 3 * DD,
                                   dlnb + (size_t)l * 3 * DD, X, Xh);

        const float* bc = dcb + (size_t)l * 4 * DD;
        gemm_h64<<<g64, 128>>>(Xh, dcWt + (size_t)l * 4 * M1, bc, Qh);
        adst = full ? out + OFF_CROSS + (size_t)l * SLAB : ATT;
        attn_scores_f16<<<gS, 256, SC_SMEM>>>(Qh, CKh + (size_t)l * M1, src_mask, 0, adst, Ph);
        attn_ctx_f16<<<gC, 256>>>(Ph, CVh + (size_t)l * M1, Qh);
        gemm_sk_h<<<gSK2, 128>>>(Qh, dcWt + ((size_t)l * 4 + 3) * M1, PRT, 1024, 1024, 512);
        add_ln_red<<<MROWS, 256>>>(X, PRT, 2, bc + 3 * DD,
                                   dlng + (size_t)l * 3 * DD + DD,
                                   dlnb + (size_t)l * 3 * DD + DD, X2, X2h);

        gemm_wide_h<<<gF1, 256, SM_W>>>(X2h, dW1t + (size_t)l * 4 * M1,
                                        db1 + (size_t)l * DFFF, H1h,
                                        DD, DFFF, 1, 0, 0, 0);
        gemm_sk_h<<<gSK4, 128>>>(H1h, dW2t + (size_t)l * 4 * M1, PRT, 4096, 4096, 1024);
        add_ln_red<<<MROWS, 256>>>(X2, PRT, 4, db2 + (size_t)l * DD,
                                   dlng + (size_t)l * 3 * DD + 2 * DD,
                                   dlnb + (size_t)l * 3 * DD + 2 * DD, X, Xh);
        cur = X; curh = Xh;
    }
    ln_plain<<<MROWS, 256>>>(cur, dfg, dfb, out, nullptr);
}

// round 15
// speedup vs baseline: 1.7076x; 1.1066x over previous
#include <cuda_runtime.h>
#include <cuda_fp16.h>
#include <cstdint>
#include <cstddef>

// ---------------------------------------------------------------------------
// Transformer forward, R15: R14 + K-step 64 cp.async GEMM pipelines
// (half the barriers per CTA, deeper prefetch).
// ---------------------------------------------------------------------------

#define BB   2
#define SS   512
#define DD   1024
#define HH   16
#define DKK  64
#define DFFF 4096
#define LL   4
#define MROWS (BB*SS)          // 1024
#define EPSF 1e-5f
#define INV_SCALE 0.125f       // 1/sqrt(DK)

static const size_t MEG = 1u << 20;
__device__ __align__(16) float g_scratch[89u * (1u << 20)];   // 356 MB

// ---------------------------------------------------------------------------
// helpers
// ---------------------------------------------------------------------------
__device__ __forceinline__ uint32_t pk(float lo, float hi) {
    __half2 h = __floats2half2_rn(lo, hi);
    return *(uint32_t*)&h;
}
__device__ __forceinline__ uint2 pk4(float4 v) {
    return make_uint2(pk(v.x, v.y), pk(v.z, v.w));
}
__device__ __forceinline__ uint4 permT(uint2 e, uint2 o) {
    uint4 r;
    r.x = __byte_perm(e.x, o.x, 0x5410);
    r.y = __byte_perm(e.x, o.x, 0x7632);
    r.z = __byte_perm(e.y, o.y, 0x5410);
    r.w = __byte_perm(e.y, o.y, 0x7632);
    return r;
}
__device__ __forceinline__ void mma16(float* c, const uint32_t* a, const uint32_t* b) {
    asm volatile(
        "mma.sync.aligned.m16n8k16.row.col.f32.f16.f16.f32 "
        "{%0,%1,%2,%3}, {%4,%5,%6,%7}, {%8,%9}, {%0,%1,%2,%3};\n"
        : "+f"(c[0]), "+f"(c[1]), "+f"(c[2]), "+f"(c[3])
        : "r"(a[0]), "r"(a[1]), "r"(a[2]), "r"(a[3]), "r"(b[0]), "r"(b[1]));
}
__device__ __forceinline__ uint32_t smaddr(const void* p) {
    return (uint32_t)__cvta_generic_to_shared(p);
}
__device__ __forceinline__ void cpa16(uint32_t dsm, const void* gsrc) {
    asm volatile("cp.async.cg.shared.global [%0], [%1], 16;" :: "r"(dsm), "l"(gsrc));
}
#define CP_COMMIT() asm volatile("cp.async.commit_group;")
#define CP_WAIT2()  asm volatile("cp.async.wait_group 2;")

// ---------------------------------------------------------------------------
// Prepass: fp32 -> fp16 convert
// ---------------------------------------------------------------------------
__global__ __launch_bounds__(256)
void cvt16(const float* __restrict__ x, __half* __restrict__ y, int n)
{
    const int i = (blockIdx.x * 256 + threadIdx.x) * 4;
    if (i < n) {
        float4 v = *(const float4*)&x[i];
        *(uint2*)&y[i] = pk4(v);
    }
}

// Batched transpose+convert W[K,N] fp32 -> Wt[N,K] fp16.
__global__ __launch_bounds__(256)
void tcvt(const float* __restrict__ src, __half* __restrict__ dst, int K, int N)
{
    const size_t zoff = (size_t)blockIdx.z * K * N;
    src += zoff; dst += zoff;
    __shared__ float tile[32][33];
    const int t = threadIdx.x;
    const int tx = (t & 7) * 4, ty = t >> 3;
    const int x0 = blockIdx.x * 32, y0 = blockIdx.y * 32;

    float4 v = *(const float4*)&src[(size_t)(y0 + ty) * N + x0 + tx];
    tile[ty][tx] = v.x; tile[ty][tx + 1] = v.y;
    tile[ty][tx + 2] = v.z; tile[ty][tx + 3] = v.w;
    __syncthreads();

    const float a = tile[tx][ty], b = tile[tx + 1][ty];
    const float c = tile[tx + 2][ty], d = tile[tx + 3][ty];
    *(uint2*)&dst[(size_t)(x0 + ty) * K + y0 + tx] = make_uint2(pk(a, b), pk(c, d));
}

// ---------------------------------------------------------------------------
// Wide GEMM: fp16 A[M][K] @ fp16 Wt[N][K] -> fp16 C (+fp32 bias, opt ReLU).
// 64x128 tile, 256 thr, cp.async 4-stage, K-step 64.
// Dyn smem 4*(64*36 + 128*36)*4 = 110592 B (2 CTAs/SM).
// ---------------------------------------------------------------------------
__global__ __launch_bounds__(256, 2)
void gemm_wide_h(const __half* __restrict__ A, const __half* __restrict__ Wt,
                 const float* __restrict__ bias, __half* __restrict__ C,
                 int K, int nb, int relu,
                 long long wstride, long long bstride, long long cstride)
{
    constexpr int ASTR = 36, BSTR = 36;
    constexpr int ASZ = 64 * ASTR, BSZ = 128 * BSTR, STG = ASZ + BSZ;  // 6912
    extern __shared__ uint32_t smg[];

    const int t = threadIdx.x, lane = t & 31, w = t >> 5;
    const int g = lane >> 2, cc = lane & 3;
    const int wm = w >> 2, wn = w & 3;
    const int row0 = blockIdx.y * 64;
    const int colg = blockIdx.x * 128;
    const int blk  = colg / nb;
    const int col0 = colg - blk * nb;
    const __half* Wp = Wt + (size_t)blk * (size_t)wstride;
    const float* bp = bias + (size_t)blk * (size_t)bstride;
    __half* Cp = C + (size_t)blk * (size_t)cstride;

    const uint32_t sb = smaddr(smg);

    auto issue = [&](int it) {
        const int k0 = it << 6;
        const uint32_t base = sb + (uint32_t)((it & 3) * STG) * 4u;
#pragma unroll
        for (int i = 0; i < 2; i++) {           // A: 64 rows x 8 chunks
            const int idx = t + i * 256;
            const int r = idx >> 3, ch = idx & 7;
            cpa16(base + (uint32_t)(r * ASTR + ch * 4) * 4u,
                  A + (size_t)(row0 + r) * K + k0 + ch * 8);
        }
#pragma unroll
        for (int i = 0; i < 4; i++) {           // B: 128 rows x 8 chunks
            const int idx = t + i * 256;
            const int br = idx >> 3, ch = idx & 7;
            cpa16(base + (uint32_t)(ASZ + br * BSTR + ch * 4) * 4u,
                  Wp + (size_t)(col0 + br) * K + k0 + ch * 8);
        }
    };

    float acc[2][4][4] = {};
    const int NK = K >> 6;
    issue(0); CP_COMMIT();
    issue(1); CP_COMMIT();
    issue(2); CP_COMMIT();

    for (int it = 0; it < NK; it++) {
        CP_WAIT2();
        __syncthreads();
        if (it + 3 < NK) issue(it + 3);
        CP_COMMIT();

        const uint32_t* as_ = smg + (it & 3) * STG;
        const uint32_t* bs_ = smg + (it & 3) * STG + ASZ;
        uint32_t af[2][4], bf[4][2];
#pragma unroll
        for (int ksi = 0; ksi < 4; ksi++) {
            const int kp = ksi * 8 + cc;
#pragma unroll
            for (int mi = 0; mi < 2; mi++) {
                const int mb = wm * 32 + mi * 16;
                af[mi][0] = as_[(mb + g) * ASTR + kp];
                af[mi][1] = as_[(mb + g + 8) * ASTR + kp];
                af[mi][2] = as_[(mb + g) * ASTR + kp + 4];
                af[mi][3] = as_[(mb + g + 8) * ASTR + kp + 4];
            }
#pragma unroll
            for (int nj = 0; nj < 4; nj++) {
                const int nrow = wn * 32 + nj * 8 + g;
                bf[nj][0] = bs_[nrow * BSTR + kp];
                bf[nj][1] = bs_[nrow * BSTR + kp + 4];
            }
#pragma unroll
            for (int mi = 0; mi < 2; mi++)
#pragma unroll
                for (int nj = 0; nj < 4; nj++)
                    mma16(acc[mi][nj], af[mi], bf[nj]);
        }
    }

#pragma unroll
    for (int mi = 0; mi < 2; mi++) {
        const int r0 = row0 + wm * 32 + mi * 16 + g;
#pragma unroll
        for (int nj = 0; nj < 4; nj++) {
            const int c = col0 + wn * 32 + nj * 8 + 2 * cc;
            const float b0v = bp[c], b1v = bp[c + 1];
            float v0 = acc[mi][nj][0] + b0v, v1 = acc[mi][nj][1] + b1v;
            float v2 = acc[mi][nj][2] + b0v, v3 = acc[mi][nj][3] + b1v;
            if (relu) {
                v0 = fmaxf(v0, 0.f); v1 = fmaxf(v1, 0.f);
                v2 = fmaxf(v2, 0.f); v3 = fmaxf(v3, 0.f);
            }
            *(uint32_t*)&Cp[(size_t)r0 * nb + c]       = pk(v0, v1);
            *(uint32_t*)&Cp[(size_t)(r0 + 8) * nb + c] = pk(v2, v3);
        }
    }
}

// ---------------------------------------------------------------------------
// 128-thread 64x64 cp.async core, K-step 64, 4-stage.
// Dyn smem 4*(64*36 + 64*36)*4 = 73728 B (3 CTAs/SM).
// ---------------------------------------------------------------------------
#define GEMMH64_CORE(AP, WP, LDA, LDW, NKV)                                     \
    constexpr int ASTR = 36, BSTR = 36;                                         \
    constexpr int ASZ = 64 * ASTR, BSZ = 64 * BSTR, STG = ASZ + BSZ;            \
    extern __shared__ uint32_t smg[];                                           \
    const int t = threadIdx.x, lane = t & 31, w = t >> 5;                       \
    const int g = lane >> 2, cc = lane & 3;                                     \
    const int wm = w >> 1, wn = w & 1;                                          \
    const int row0 = blockIdx.y * 64;                                           \
    const int col0 = blockIdx.x * 64;                                           \
    const uint32_t sb = smaddr(smg);                                            \
    auto issue = [&](int it) {                                                  \
        const int k0 = it << 6;                                                 \
        const uint32_t base = sb + (uint32_t)((it & 3) * STG) * 4u;             \
        _Pragma("unroll")                                                       \
        for (int i = 0; i < 4; i++) {                                           \
            const int idx = t + i * 128;                                        \
            const int r = idx >> 3, ch = idx & 7;                               \
            cpa16(base + (uint32_t)(r * ASTR + ch * 4) * 4u,                    \
                  AP + (size_t)(row0 + r) * LDA + k0 + ch * 8);                 \
            cpa16(base + (uint32_t)(ASZ + r * BSTR + ch * 4) * 4u,              \
                  WP + (size_t)(col0 + r) * LDW + k0 + ch * 8);                 \
        }                                                                       \
    };                                                                          \
    float acc[2][4][4] = {};                                                    \
    const int NK = (NKV);                                                       \
    issue(0); CP_COMMIT();                                                      \
    issue(1); CP_COMMIT();                                                      \
    issue(2); CP_COMMIT();                                                      \
    for (int it = 0; it < NK; it++) {                                           \
        CP_WAIT2();                                                             \
        __syncthreads();                                                        \
        if (it + 3 < NK) issue(it + 3);                                         \
        CP_COMMIT();                                                            \
        const uint32_t* as_ = smg + (it & 3) * STG;                             \
        const uint32_t* bs_ = smg + (it & 3) * STG + ASZ;                       \
        uint32_t af[2][4], bf[4][2];                                            \
        _Pragma("unroll")                                                       \
        for (int ksi = 0; ksi < 4; ksi++) {                                     \
            const int kp = ksi * 8 + cc;                                        \
            _Pragma("unroll")                                                   \
            for (int mi = 0; mi < 2; mi++) {                                    \
                const int mb = wm * 32 + mi * 16;                               \
                af[mi][0] = as_[(mb + g) * ASTR + kp];                          \
                af[mi][1] = as_[(mb + g + 8) * ASTR + kp];                      \
                af[mi][2] = as_[(mb + g) * ASTR + kp + 4];                      \
                af[mi][3] = as_[(mb + g + 8) * ASTR + kp + 4];                  \
            }                                                                   \
            _Pragma("unroll")                                                   \
            for (int nj = 0; nj < 4; nj++) {                                    \
                const int nrow = wn * 32 + nj * 8 + g;                          \
                bf[nj][0] = bs_[nrow * BSTR + kp];                              \
                bf[nj][1] = bs_[nrow * BSTR + kp + 4];                          \
            }                                                                   \
            _Pragma("unroll")                                                   \
            for (int mi = 0; mi < 2; mi++)                                      \
                _Pragma("unroll")                                               \
                for (int nj = 0; nj < 4; nj++)                                  \
                    mma16(acc[mi][nj], af[mi], bf[nj]);                         \
        }                                                                       \
    }

// cross-Q: fp16 A @ Wt + bias -> fp16 C.
__global__ __launch_bounds__(128, 3)
void gemm_h64(const __half* __restrict__ A, const __half* __restrict__ Wt,
              const float* __restrict__ bias, __half* __restrict__ C)
{
    GEMMH64_CORE(A, Wt, 1024, 1024, 16)
#pragma unroll
    for (int mi = 0; mi < 2; mi++) {
        const int r0 = row0 + wm * 32 + mi * 16 + g;
#pragma unroll
        for (int nj = 0; nj < 4; nj++) {
            const int c = col0 + wn * 32 + nj * 8 + 2 * cc;
            const float b0v = bias[c], b1v = bias[c + 1];
            *(uint32_t*)&C[(size_t)r0 * 1024 + c] =
                pk(acc[mi][nj][0] + b0v, acc[mi][nj][1] + b1v);
            *(uint32_t*)&C[(size_t)(r0 + 8) * 1024 + c] =
                pk(acc[mi][nj][2] + b0v, acc[mi][nj][3] + b1v);
        }
    }
}

// Split-K: parts[z] = A[:, zKc:(z+1)Kc] @ Wt-cols-slice. Grid (16,16,nsplit).
__global__ __launch_bounds__(128, 3)
void gemm_sk_h(const __half* __restrict__ A, const __half* __restrict__ Wt,
               float* __restrict__ parts, int lda, int ldw, int Kc)
{
    const int z = blockIdx.z;
    const __half* Az = A + (size_t)z * Kc;
    const __half* Wz = Wt + (size_t)z * Kc;
    float* Cp = parts + (size_t)z * MEG;
    GEMMH64_CORE(Az, Wz, lda, ldw, (Kc >> 6))
#pragma unroll
    for (int mi = 0; mi < 2; mi++) {
        const int r0 = row0 + wm * 32 + mi * 16 + g;
#pragma unroll
        for (int nj = 0; nj < 4; nj++) {
            const int c = col0 + wn * 32 + nj * 8 + 2 * cc;
            *(float2*)&Cp[(size_t)r0 * 1024 + c] =
                make_float2(acc[mi][nj][0], acc[mi][nj][1]);
            *(float2*)&Cp[(size_t)(r0 + 8) * 1024 + c] =
                make_float2(acc[mi][nj][2], acc[mi][nj][3]);
        }
    }
}

// ---------------------------------------------------------------------------
// LayerNorm (one-pass, float4 vectorized). Writes fp32 y and optional fp16 yh.
// ---------------------------------------------------------------------------
__device__ __forceinline__ void block_reduce2(float& s, float& s2,
                                              float* sh1, float* sh2,
                                              int lane, int w)
{
#pragma unroll
    for (int o = 16; o > 0; o >>= 1) {
        s  += __shfl_xor_sync(0xffffffffu, s, o);
        s2 += __shfl_xor_sync(0xffffffffu, s2, o);
    }
    if (lane == 0) { sh1[w] = s; sh2[w] = s2; }
    __syncthreads();
    if (w == 0) {
        float a = (lane < 8) ? sh1[lane] : 0.f;
        float b = (lane < 8) ? sh2[lane] : 0.f;
#pragma unroll
        for (int o = 4; o > 0; o >>= 1) {
            a += __shfl_xor_sync(0xffffffffu, a, o);
            b += __shfl_xor_sync(0xffffffffu, b, o);
        }
        if (lane == 0) { sh1[0] = a; sh2[0] = b; }
    }
    __syncthreads();
}

__global__ __launch_bounds__(256)
void add_ln_red(const float* __restrict__ x, const float* __restrict__ parts,
                int nparts, const float* __restrict__ bias,
                const float* __restrict__ g, const float* __restrict__ bt,
                float* __restrict__ y, __half* __restrict__ yh)
{
    const int row = blockIdx.x;
    const int t = threadIdx.x;
    const int lane = t & 31, w = t >> 5;
    __shared__ float sh1[8], sh2[8];

    const int c = t * 4;
    const size_t idx = (size_t)row * DD + c;
    float4 v  = *(const float4*)&x[idx];
    float4 bv = *(const float4*)&bias[c];
    v.x += bv.x; v.y += bv.y; v.z += bv.z; v.w += bv.w;
    for (int p = 0; p < nparts; p++) {
        float4 q = *(const float4*)&parts[(size_t)p * MEG + idx];
        v.x += q.x; v.y += q.y; v.z += q.z; v.w += q.w;
    }
    float s  = v.x + v.y + v.z + v.w;
    float s2 = v.x * v.x + v.y * v.y + v.z * v.z + v.w * v.w;
    block_reduce2(s, s2, sh1, sh2, lane, w);
    const float mean = sh1[0] * (1.0f / DD);
    const float var  = sh2[0] * (1.0f / DD) - mean * mean;
    const float inv  = rsqrtf(var + EPSF);

    float4 gv = *(const float4*)&g[c];
    float4 tv = *(const float4*)&bt[c];
    float4 r;
    r.x = gv.x * (v.x - mean) * inv + tv.x;
    r.y = gv.y * (v.y - mean) * inv + tv.y;
    r.z = gv.z * (v.z - mean) * inv + tv.z;
    r.w = gv.w * (v.w - mean) * inv + tv.w;
    *(float4*)&y[idx] = r;
    if (yh) *(uint2*)&yh[idx] = pk4(r);
}

__global__ __launch_bounds__(256)
void ln_plain(const float* __restrict__ x, const float* __restrict__ g,
              const float* __restrict__ bt, float* __restrict__ y,
              __half* __restrict__ yh)
{
    const int row = blockIdx.x;
    const int t = threadIdx.x;
    const int lane = t & 31, w = t >> 5;
    __shared__ float sh1[8], sh2[8];

    const int c = t * 4;
    const size_t idx = (size_t)row * DD + c;
    float4 v = *(const float4*)&x[idx];
    float s  = v.x + v.y + v.z + v.w;
    float s2 = v.x * v.x + v.y * v.y + v.z * v.z + v.w * v.w;
    block_reduce2(s, s2, sh1, sh2, lane, w);
    const float mean = sh1[0] * (1.0f / DD);
    const float var  = sh2[0] * (1.0f / DD) - mean * mean;
    const float inv  = rsqrtf(var + EPSF);

    float4 gv = *(const float4*)&g[c];
    float4 tv = *(const float4*)&bt[c];
    float4 r;
    r.x = gv.x * (v.x - mean) * inv + tv.x;
    r.y = gv.y * (v.y - mean) * inv + tv.y;
    r.z = gv.z * (v.z - mean) * inv + tv.z;
    r.w = gv.w * (v.w - mean) * inv + tv.w;
    *(float4*)&y[idx] = r;
    if (yh) *(uint2*)&yh[idx] = pk4(r);
}

// ---------------------------------------------------------------------------
// Scores + mask + softmax. 32 q-rows per CTA (512 CTAs, ~80 KB smem).
// Writes P fp32 to attn (output) and fp16 to ph (feeds ctx).
// ---------------------------------------------------------------------------
__global__ __launch_bounds__(256)
void attn_scores_f16(const __half* __restrict__ qf,
                     const __half* __restrict__ kf,
                     const int* __restrict__ mask,
                     int causal,
                     float* __restrict__ attn,
                     __half* __restrict__ ph)
{
    extern __shared__ float smemf[];
    uint32_t* Qs = (uint32_t*)smemf;        // 32*36
    uint32_t* Ks = Qs + 32 * 36;            // 64*36
    float* Ssm = smemf + (32 + 64) * 36;    // 32*516

    const int bh = blockIdx.y, b = bh >> 4, h = bh & 15;
    const int q0 = blockIdx.x * 32;
    const int t = threadIdx.x, lane = t & 31, w = t >> 5;
    const int g = lane >> 2, cc = lane & 3;
    const int qslot = w >> 2, kslot = w & 3;

    {
        const int r = t >> 3, ch = t & 7;
        uint4 v = *(const uint4*)&qf[(size_t)(b * SS + q0 + r) * DD + h * DKK + ch * 8];
        *(uint4*)&Qs[r * 36 + ch * 4] = v;
    }

    int mreg[16];
    if (!causal) {
#pragma unroll
        for (int j = 0; j < 16; j++)
            mreg[j] = mask[(size_t)b * SS + lane + j * 32];
    }

    for (int kt = 0; kt < 8; kt++) {
        __syncthreads();
#pragma unroll
        for (int i = 0; i < 2; i++) {
            const int idx = t + i * 256;
            const int r = idx >> 3, ch = idx & 7;
            uint4 v = *(const uint4*)&kf[(size_t)(b * SS + kt * 64 + r) * DD + h * DKK + ch * 8];
            *(uint4*)&Ks[r * 36 + ch * 4] = v;
        }
        __syncthreads();

        float acc[2][4] = {};
        uint32_t af[4];
#pragma unroll
        for (int ksi = 0; ksi < 4; ksi++) {
            const int kp = ksi * 8 + cc;
            const int mb = qslot * 16;
            af[0] = Qs[(mb + g) * 36 + kp];
            af[1] = Qs[(mb + g + 8) * 36 + kp];
            af[2] = Qs[(mb + g) * 36 + kp + 4];
            af[3] = Qs[(mb + g + 8) * 36 + kp + 4];
#pragma unroll
            for (int nj = 0; nj < 2; nj++) {
                const int nbase = kslot * 16 + nj * 8;
                uint32_t bf[2];
                bf[0] = Ks[(nbase + g) * 36 + kp];
                bf[1] = Ks[(nbase + g) * 36 + kp + 4];
                mma16(acc[nj], af, bf);
            }
        }
#pragma unroll
        for (int nj = 0; nj < 2; nj++) {
            const int colb = kt * 64 + kslot * 16 + nj * 8 + 2 * cc;
            const int rr = qslot * 16 + g;
            *(float2*)&Ssm[rr * 516 + colb]       = make_float2(acc[nj][0], acc[nj][1]);
            *(float2*)&Ssm[(rr + 8) * 516 + colb] = make_float2(acc[nj][2], acc[nj][3]);
        }
    }
    __syncthreads();

    for (int i = 0; i < 4; i++) {
        const int rloc = w * 4 + i;
        const int q = q0 + rloc;
        float vals[16];
        float mx = -1e30f;
#pragma unroll
        for (int j = 0; j < 16; j++) {
            const int col = lane + j * 32;
            float v = Ssm[rloc * 516 + col] * INV_SCALE;
            const int m = causal ? mask[((size_t)b * SS + q) * SS + col] : mreg[j];
            if (m == 0) v = -1e9f;
            vals[j] = v;
            mx = fmaxf(mx, v);
        }
#pragma unroll
        for (int o = 16; o > 0; o >>= 1)
            mx = fmaxf(mx, __shfl_xor_sync(0xffffffffu, mx, o));
        float sum = 0.0f;
#pragma unroll
        for (int j = 0; j < 16; j++) {
            vals[j] = expf(vals[j] - mx);
            sum += vals[j];
        }
#pragma unroll
        for (int o = 16; o > 0; o >>= 1)
            sum += __shfl_xor_sync(0xffffffffu, sum, o);
        const float inv = 1.0f / sum;
        float* dst = attn + ((size_t)bh * SS + q) * SS;
        __half* dsth = ph + ((size_t)bh * SS + q) * SS;
#pragma unroll
        for (int j = 0; j < 16; j++) {
            const float p = vals[j] * inv;
            dst[lane + j * 32] = p;
            dsth[lane + j * 32] = __float2half_rn(p);
        }
    }
}

// ---------------------------------------------------------------------------
// Context: P fp16 @ V fp16 -> ctx fp16. Double-buffered K-step 32.
// ---------------------------------------------------------------------------
__global__ __launch_bounds__(256)
void attn_ctx_f16(const __half* __restrict__ ph,
                  const __half* __restrict__ vf,
                  __half* __restrict__ ctx)
{
    constexpr int ASTR = 20, BSTR = 72;
    constexpr int ASZ = 64 * ASTR, BSZ = 16 * BSTR, STG = ASZ + BSZ;
    __shared__ uint32_t smg2[2 * STG];

    const int bh = blockIdx.y, b = bh >> 4, h = bh & 15;
    const int q0 = blockIdx.x * 64;
    const int t = threadIdx.x, lane = t & 31, w = t >> 5;
    const int g = lane >> 2, cc = lane & 3;
    const int qslot = w & 3, dslot = w >> 2;
    const __half* Ap = ph + (size_t)bh * SS * SS;
    const __half* Vp = vf + (size_t)b * SS * DD + h * DKK;

    const int ar = t >> 3, ac = (t & 7) << 2;
    const int vr = t >> 4, vc = (t & 15) << 2;

    uint2 aR[2], vE, vO;
    auto loadAB = [&](int k0) {
#pragma unroll
        for (int i = 0; i < 2; i++)
            aR[i] = *(const uint2*)&Ap[(size_t)(q0 + ar + i * 32) * SS + k0 + ac];
        vE = *(const uint2*)&Vp[(size_t)(k0 + 2 * vr) * DD + vc];
        vO = *(const uint2*)&Vp[(size_t)(k0 + 2 * vr + 1) * DD + vc];
    };
    auto storeAB = [&](int p) {
        uint32_t* as_ = smg2 + p * STG;
        uint32_t* bs_ = smg2 + p * STG + ASZ;
#pragma unroll
        for (int i = 0; i < 2; i++)
            *(uint2*)&as_[(ar + i * 32) * ASTR + (ac >> 1)] = aR[i];
        *(uint4*)&bs_[vr * BSTR + vc] = permT(vE, vO);
    };

    float acc[4][4] = {};
    const int NK = 16;
    loadAB(0);
    storeAB(0);
    loadAB(32);
    __syncthreads();

    for (int it = 0; it < NK; it++) {
        const int p = it & 1;
        if (it + 1 < NK) storeAB(p ^ 1);
        if (it + 2 < NK) loadAB((it + 2) << 5);

        const uint32_t* as_ = smg2 + p * STG;
        const uint32_t* bs_ = smg2 + p * STG + ASZ;
        uint32_t af[4], bf[2];
#pragma unroll
        for (int ksi = 0; ksi < 2; ksi++) {
            const int kp = ksi * 8 + cc;
            const int mb = qslot * 16;
            af[0] = as_[(mb + g) * ASTR + kp];
            af[1] = as_[(mb + g + 8) * ASTR + kp];
            af[2] = as_[(mb + g) * ASTR + kp + 4];
            af[3] = as_[(mb + g + 8) * ASTR + kp + 4];
#pragma unroll
            for (int nj = 0; nj < 4; nj++) {
                const int nbase = dslot * 32 + nj * 8;
                bf[0] = bs_[kp * BSTR + nbase + g];
                bf[1] = bs_[(kp + 4) * BSTR + nbase + g];
                mma16(acc[nj], af, bf);
            }
        }
        __syncthreads();
    }

    __half* Cp = ctx + (size_t)b * SS * DD + h * DKK;
#pragma unroll
    for (int nj = 0; nj < 4; nj++) {
        const int c = dslot * 32 + nj * 8 + 2 * cc;
        const int r = q0 + qslot * 16 + g;
        *(uint32_t*)&Cp[(size_t)r * DD + c]       = pk(acc[nj][0], acc[nj][1]);
        *(uint32_t*)&Cp[(size_t)(r + 8) * DD + c] = pk(acc[nj][2], acc[nj][3]);
    }
}

// ---------------------------------------------------------------------------
// Host orchestration
// ---------------------------------------------------------------------------
extern "C" void kernel_launch(void* const* d_in, const int* in_sizes, int n_in,
                              void* d_out, int out_size)
{
    const float* src     = (const float*)d_in[0];
    const float* tgt     = (const float*)d_in[1];
    const float* enc_W   = (const float*)d_in[2];
    const float* enc_b   = (const float*)d_in[3];
    const float* enc_W1  = (const float*)d_in[4];
    const float* enc_b1  = (const float*)d_in[5];
    const float* enc_W2  = (const float*)d_in[6];
    const float* enc_b2  = (const float*)d_in[7];
    const float* enc_lng = (const float*)d_in[8];
    const float* enc_lnb = (const float*)d_in[9];
    const float* enc_fg  = (const float*)d_in[10];
    const float* enc_fb  = (const float*)d_in[11];
    const float* dsW     = (const float*)d_in[12];
    const float* dsb     = (const float*)d_in[13];
    const float* dcW     = (const float*)d_in[14];
    const float* dcb     = (const float*)d_in[15];
    const float* dW1     = (const float*)d_in[16];
    const float* db1     = (const float*)d_in[17];
    const float* dW2     = (const float*)d_in[18];
    const float* db2     = (const float*)d_in[19];
    const float* dlng    = (const float*)d_in[20];
    const float* dlnb    = (const float*)d_in[21];
    const float* dfg     = (const float*)d_in[22];
    const float* dfb     = (const float*)d_in[23];
    const int*   src_mask = (const int*)d_in[24];
    const int*   tgt_mask = (const int*)d_in[25];
    float* out = (float*)d_out;

    float* scratch = nullptr;
    cudaGetSymbolAddress((void**)&scratch, g_scratch);

    float*  X    = scratch + 0 * MEG;
    float*  X2   = scratch + 1 * MEG;
    __half* Qh   = (__half*)(scratch + 2 * MEG);   // Q,K,V: 3M halves
    __half* H1h  = (__half*)(scratch + 4 * MEG);   // 4M halves
    __half* Xh   = (__half*)(scratch + 6 * MEG);
    __half* X2h  = (__half*)(scratch + 7 * MEG);
    __half* srch = (__half*)(scratch + 8 * MEG);
    __half* tgth = (__half*)(scratch + 9 * MEG);
    __half* ENCh = (__half*)(scratch + 10 * MEG);
    float*  ATT  = scratch + 11 * MEG;             // 8M floats (fallback)
    float*  ENC  = scratch + 19 * MEG;
    float*  PRT  = scratch + 20 * MEG;             // 4M floats
    __half* CKh  = (__half*)(scratch + 24 * MEG);  // 4M halves
    __half* CVh  = (__half*)(scratch + 26 * MEG);  // 4M halves
    __half* WH   = (__half*)(scratch + 28 * MEG);  // 112M halves
    __half* Ph   = (__half*)(scratch + 84 * MEG);  // 8.4M halves (P fp16)

    const size_t M1 = MEG;
    __half* encWt = WH;                 // [L*4][1024][1024]
    __half* dsWt  = WH + 16 * M1;
    __half* dcWt  = WH + 32 * M1;
    __half* eW1t  = WH + 48 * M1;       // [L][4096][1024]
    __half* eW2t  = WH + 64 * M1;       // [L][1024][4096]
    __half* dW1t  = WH + 80 * M1;
    __half* dW2t  = WH + 96 * M1;

    const size_t SLAB      = (size_t)BB * HH * SS * SS;
    const size_t OFF_ENC   = (size_t)BB * SS * DD;
    const size_t OFF_SELF  = OFF_ENC + (size_t)LL * SLAB;
    const size_t OFF_CROSS = OFF_SELF + (size_t)LL * SLAB;
    const size_t TOTAL     = OFF_CROSS + (size_t)LL * SLAB;
    const bool full = ((size_t)out_size >= TOTAL);

    const int SM_W   = 4 * (64 * 36 + 128 * 36) * 4;  // 110592 B
    const int SM_G64 = 4 * (64 * 36 + 64 * 36) * 4;   // 73728 B
    cudaFuncSetAttribute(gemm_wide_h, cudaFuncAttributeMaxDynamicSharedMemorySize, SM_W);
    cudaFuncSetAttribute(gemm_h64, cudaFuncAttributeMaxDynamicSharedMemorySize, SM_G64);
    cudaFuncSetAttribute(gemm_sk_h, cudaFuncAttributeMaxDynamicSharedMemorySize, SM_G64);
    const size_t SC_SMEM = (size_t)((32 + 64) * 36 + 32 * 516) * sizeof(float);
    cudaFuncSetAttribute(attn_scores_f16,
                         cudaFuncAttributeMaxDynamicSharedMemorySize, (int)SC_SMEM);

    // ---------------- Prepass ----------------
    cvt16<<<1024, 256>>>(src, srch, MROWS * DD);
    cvt16<<<1024, 256>>>(tgt, tgth, MROWS * DD);
    tcvt<<<dim3(32, 32, 16), 256>>>(enc_W, encWt, 1024, 1024);
    tcvt<<<dim3(32, 32, 16), 256>>>(dsW, dsWt, 1024, 1024);
    tcvt<<<dim3(32, 32, 16), 256>>>(dcW, dcWt, 1024, 1024);
    tcvt<<<dim3(128, 32, 4), 256>>>(enc_W1, eW1t, 1024, 4096);
    tcvt<<<dim3(32, 128, 4), 256>>>(enc_W2, eW2t, 4096, 1024);
    tcvt<<<dim3(128, 32, 4), 256>>>(dW1, dW1t, 1024, 4096);
    tcvt<<<dim3(32, 128, 4), 256>>>(dW2, dW2t, 4096, 1024);

    dim3 gQKV(3072 / 128, MROWS / 64);   // 384 CTAs
    dim3 gKVB(4096 / 128, MROWS / 64);   // 512 CTAs
    dim3 gF1(DFFF / 128, MROWS / 64);    // 512 CTAs
    dim3 g64(16, 16);                    // 256 CTAs
    dim3 gSK2(16, 16, 2);
    dim3 gSK4(16, 16, 4);
    dim3 gS(SS / 32, BB * HH);           // 512 CTAs
    dim3 gC(SS / 64, BB * HH);

    // ------------------------- Encoder -------------------------
    const float* cur = src;
    const __half* curh = srch;
    for (int l = 0; l < LL; l++) {
        const float* bb = enc_b + (size_t)l * 4 * DD;
        gemm_wide_h<<<gQKV, 256, SM_W>>>(curh, encWt + (size_t)l * 4 * M1, bb, Qh,
                                         DD, DD, 0, (long long)M1, DD, (long long)M1);
        float* adst = full ? out + OFF_ENC + (size_t)l * SLAB : ATT;
        attn_scores_f16<<<gS, 256, SC_SMEM>>>(Qh, Qh + M1, src_mask, 0, adst, Ph);
        attn_ctx_f16<<<gC, 256>>>(Ph, Qh + 2 * M1, Qh);
        gemm_sk_h<<<gSK2, 128, SM_G64>>>(Qh, encWt + ((size_t)l * 4 + 3) * M1, PRT, 1024, 1024, 512);
        add_ln_red<<<MROWS, 256>>>(cur, PRT, 2, bb + 3 * DD,
                                   enc_lng + (size_t)l * 2 * DD,
                                   enc_lnb + (size_t)l * 2 * DD, X2, X2h);
        gemm_wide_h<<<gF1, 256, SM_W>>>(X2h, eW1t + (size_t)l * 4 * M1,
                                        enc_b1 + (size_t)l * DFFF, H1h,
                                        DD, DFFF, 1, 0, 0, 0);
        gemm_sk_h<<<gSK4, 128, SM_G64>>>(H1h, eW2t + (size_t)l * 4 * M1, PRT, 4096, 4096, 1024);
        add_ln_red<<<MROWS, 256>>>(X2, PRT, 4, enc_b2 + (size_t)l * DD,
                                   enc_lng + (size_t)l * 2 * DD + DD,
                                   enc_lnb + (size_t)l * 2 * DD + DD, X, Xh);
        cur = X; curh = Xh;
    }
    ln_plain<<<MROWS, 256>>>(cur, enc_fg, enc_fb, ENC, ENCh);

    // Batched cross-attention K/V (blk = layer)
    gemm_wide_h<<<gKVB, 256, SM_W>>>(ENCh, dcWt + M1, dcb + DD, CKh,
                                     DD, DD, 0, 4LL * M1, 4LL * DD, (long long)M1);
    gemm_wide_h<<<gKVB, 256, SM_W>>>(ENCh, dcWt + 2 * M1, dcb + 2 * DD, CVh,
                                     DD, DD, 0, 4LL * M1, 4LL * DD, (long long)M1);

    // ------------------------- Decoder -------------------------
    cur = tgt; curh = tgth;
    for (int l = 0; l < LL; l++) {
        const float* bs = dsb + (size_t)l * 4 * DD;
        gemm_wide_h<<<gQKV, 256, SM_W>>>(curh, dsWt + (size_t)l * 4 * M1, bs, Qh,
                                         DD, DD, 0, (long long)M1, DD, (long long)M1);
        float* adst = full ? out + OFF_SELF + (size_t)l * SLAB : ATT;
        attn_scores_f16<<<gS, 256, SC_SMEM>>>(Qh, Qh + M1, tgt_mask, 1, adst, Ph);
        attn_ctx_f16<<<gC, 256>>>(Ph, Qh + 2 * M1, Qh);
        gemm_sk_h<<<gSK2, 128, SM_G64>>>(Qh, dsWt + ((size_t)l * 4 + 3) * M1, PRT, 1024, 1024, 512);
        add_ln_red<<<MROWS, 256>>>(cur, PRT, 2, bs + 3 * DD,
                                   dlng + (size_t)l * 3 * DD,
                                   dlnb + (size_t)l * 3 * DD, X, Xh);

        const float* bc = dcb + (size_t)l * 4 * DD;
        gemm_h64<<<g64, 128, SM_G64>>>(Xh, dcWt + (size_t)l * 4 * M1, bc, Qh);
        adst = full ? out + OFF_CROSS + (size_t)l * SLAB : ATT;
        attn_scores_f16<<<gS, 256, SC_SMEM>>>(Qh, CKh + (size_t)l * M1, src_mask, 0, adst, Ph);
        attn_ctx_f16<<<gC, 256>>>(Ph, CVh + (size_t)l * M1, Qh);
        gemm_sk_h<<<gSK2, 128, SM_G64>>>(Qh, dcWt + ((size_t)l * 4 + 3) * M1, PRT, 1024, 1024, 512);
        add_ln_red<<<MROWS, 256>>>(X, PRT, 2, bc + 3 * DD,
                                   dlng + (size_t)l * 3 * DD + DD,
                                   dlnb + (size_t)l * 3 * DD + DD, X2, X2h);

        gemm_wide_h<<<gF1, 256, SM_W>>>(X2h, dW1t + (size_t)l * 4 * M1,
                                        db1 + (size_t)l * DFFF, H1h,
                                        DD, DFFF, 1, 0, 0, 0);
        gemm_sk_h<<<gSK4, 128, SM_G64>>>(H1h, dW2t + (size_t)l * 4 * M1, PRT, 4096, 4096, 1024);
        add_ln_red<<<MROWS, 256>>>(X2, PRT, 4, db2 + (size_t)l * DD,
                                   dlng + (size_t)l * 3 * DD + 2 * DD,
                                   dlnb + (size_t)l * 3 * DD + 2 * DD, X, Xh);
        cur = X; curh = Xh;
    }
    ln_plain<<<MROWS, 256>>>(cur, dfg, dfb, out, nullptr);
}